// round 7
// baseline (speedup 1.0000x reference)
#include <cuda_runtime.h>
#include <cuda_bf16.h>
#include <cstdint>

#define NROWS 65536
#define DDIM  256
#define NCB   8
#define KCB   1024
#define BM    128
#define TPB   512
#define NBLOCKS (NROWS / BM)     // 512
#define NKT   6                  // 6 x 128 bf16 k-cols = K_ext 768

// -------- device scratch --------
__device__ float         g_res[(size_t)NROWS * DDIM];        // 64 MB
__device__ __nv_bfloat16 g_A[(size_t)NROWS * 512];           // [row][a1(256)|a2(256)]
__device__ __nv_bfloat16 g_Bs[(size_t)NCB * KCB * 512];      // [ck][b1(256)|b2(256)]
__device__ float         g_ww[NCB * KCB];
__device__ double        g_lp[NCB * NBLOCKS];

// -------- smem layout (bytes) --------
#define SO_SIDX 0        // 128 int
#define SO_RR   512      // 128 f
#define SO_QS   1024     // 512 f (reused as lp)
#define SO_WW   4096     // 1024 f
#define SO_TILE 8192     // 3 stages x (A 32KB + B 32KB); reused as cand arrays
#define STAGEB  65536
#define SMEMB   (SO_TILE + 3 * STAGEB)   // 204800

__device__ __forceinline__ uint32_t smem_u32(const void* p) {
    uint32_t a;
    asm("{ .reg .u64 t; cvta.to.shared.u64 t, %1; cvt.u32.u64 %0, t; }" : "=r"(a) : "l"(p));
    return a;
}
__device__ __forceinline__ void cp16(uint32_t dst, const void* src) {
    asm volatile("cp.async.cg.shared.global [%0], [%1], 16;" :: "r"(dst), "l"(src));
}
#define CP_COMMIT() asm volatile("cp.async.commit_group;" ::: "memory")
#define CP_WAIT(n)  asm volatile("cp.async.wait_group %0;" :: "n"(n) : "memory")

__device__ __forceinline__ void ldsm4(uint32_t* r, uint32_t addr) {
    asm volatile("ldmatrix.sync.aligned.m8n8.x4.shared.b16 {%0,%1,%2,%3}, [%4];"
        : "=r"(r[0]), "=r"(r[1]), "=r"(r[2]), "=r"(r[3]) : "r"(addr));
}
__device__ __forceinline__ void mma16816(float* d, const uint32_t* a, uint32_t b0, uint32_t b1) {
    asm volatile(
        "mma.sync.aligned.m16n8k16.row.col.f32.bf16.bf16.f32 "
        "{%0,%1,%2,%3}, {%4,%5,%6,%7}, {%8,%9}, {%0,%1,%2,%3};"
        : "+f"(d[0]), "+f"(d[1]), "+f"(d[2]), "+f"(d[3])
        : "r"(a[0]), "r"(a[1]), "r"(a[2]), "r"(a[3]), "r"(b0), "r"(b1));
}
__device__ __forceinline__ void split2(float x, __nv_bfloat16& p1, __nv_bfloat16& p2) {
    p1 = __float2bfloat16_rn(x);
    p2 = __float2bfloat16_rn(x - __bfloat162float(p1));
}
// keep sorted-ascending best-4 (lexicographic on (val, idx))
__device__ __forceinline__ void upd4(float* v, int* ix, float nv, int ni) {
    if (nv > v[3] || (nv == v[3] && ni > ix[3])) return;
    v[3] = nv; ix[3] = ni;
    #pragma unroll
    for (int p = 3; p > 0; p--) {
        bool sw = (v[p] < v[p-1]) || (v[p] == v[p-1] && ix[p] < ix[p-1]);
        if (sw) {
            float tv = v[p]; v[p] = v[p-1]; v[p-1] = tv;
            int   ti = ix[p]; ix[p] = ix[p-1]; ix[p-1] = ti;
        }
    }
}

// ---- prep kernels ----
__global__ void rvq_splitA_kernel(const float* __restrict__ z)
{
    int id = blockIdx.x * 256 + threadIdx.x;
    int row = id >> 6, d4 = id & 63;
    float4 v = *(const float4*)(z + (size_t)row * DDIM + d4 * 4);
    __nv_bfloat16 p1[4], p2[4];
    split2(v.x, p1[0], p2[0]); split2(v.y, p1[1], p2[1]);
    split2(v.z, p1[2], p2[2]); split2(v.w, p1[3], p2[3]);
    __nv_bfloat16* a = g_A + (size_t)row * 512 + d4 * 4;
    *(uint64_t*)(a)       = *(uint64_t*)p1;
    *(uint64_t*)(a + 256) = *(uint64_t*)p2;
}
__global__ void rvq_splitB_kernel(const float* __restrict__ cb)
{
    int id = blockIdx.x * 256 + threadIdx.x;
    int ck = id >> 6, d4 = id & 63;
    float4 v = *(const float4*)(cb + (size_t)ck * DDIM + d4 * 4);
    __nv_bfloat16 p1[4], p2[4];
    split2(v.x, p1[0], p2[0]); split2(v.y, p1[1], p2[1]);
    split2(v.z, p1[2], p2[2]); split2(v.w, p1[3], p2[3]);
    __nv_bfloat16* b = g_Bs + (size_t)ck * 512 + d4 * 4;
    *(uint64_t*)(b)       = *(uint64_t*)p1;
    *(uint64_t*)(b + 256) = *(uint64_t*)p2;
}
__global__ void rvq_ww_kernel(const float* __restrict__ cb)
{
    const int warp = threadIdx.x >> 5, lane = threadIdx.x & 31;
    const int k = blockIdx.x * 8 + warp;
    const float* w = cb + (size_t)k * DDIM;
    float s = 0.f;
    #pragma unroll
    for (int t = 0; t < 8; t++) { float v = w[lane + 32 * t]; s = fmaf(v, v, s); }
    #pragma unroll
    for (int o = 16; o; o >>= 1) s += __shfl_down_sync(0xffffffffu, s, o);
    if (lane == 0) g_ww[k] = s;
}

// ---- fused HMMA stage: approx GEMM filter + exact rescore ----
__global__ void __launch_bounds__(TPB)
rvq_stage_kernel(const float* __restrict__ z, const float* __restrict__ cb,
                 float* __restrict__ qOut, float* __restrict__ idxOut, int c)
{
    extern __shared__ char smc[];
    const uint32_t sb = smem_u32(smc);
    int*   sIdx = (int*)(smc + SO_SIDX);
    float* rrsh = (float*)(smc + SO_RR);
    float* qs   = (float*)(smc + SO_QS);
    float* wws  = (float*)(smc + SO_WW);

    const int tid  = threadIdx.x;
    const int lane = tid & 31;
    const int warp = tid >> 5;
    const int wr   = warp >> 2;      // 0..3 (32-row slice)
    const int wc   = warp & 3;       // 0..3 (32-col slice)
    const size_t rowbase = (size_t)blockIdx.x * BM;
    const float* resIn = (c == 0) ? z : g_res;
    const float* cbc = cb + (size_t)c * KCB * DDIM;

    for (int i = tid; i < KCB; i += TPB) wws[i] = g_ww[c * KCB + i];

    // approx rr per row (4 threads/row) — only feeds the filter
    {
        int row = tid >> 2, q = tid & 3;
        const float* rp = resIn + (rowbase + row) * DDIM + q * 64;
        float s = 0.f;
        #pragma unroll
        for (int i = 0; i < 16; i++) {
            float4 v = *(const float4*)(rp + i * 4);
            s = fmaf(v.x, v.x, s); s = fmaf(v.y, v.y, s);
            s = fmaf(v.z, v.z, s); s = fmaf(v.w, v.w, s);
        }
        qs[tid] = s;
    }
    __syncthreads();
    if (tid < BM)
        rrsh[tid] = qs[tid * 4] + qs[tid * 4 + 1] + qs[tid * 4 + 2] + qs[tid * 4 + 3];
    __syncthreads();

    const int g = lane >> 2;
    float rrl[4];
    #pragma unroll
    for (int mf = 0; mf < 2; mf++)
        #pragma unroll
        for (int h = 0; h < 2; h++)
            rrl[mf * 2 + h] = rrsh[wr * 32 + mf * 16 + g + 8 * h];

    // per-thread best-4 per owned row (4 rows/thread)
    float cv4[16]; int ci4[16];
    #pragma unroll
    for (int i = 0; i < 16; i++) { cv4[i] = 3.0e38f; ci4[i] = 0x7fffffff; }

    const int arow0 = wr * 32 + (lane & 15);
    const int ukA = lane >> 4;
    const int ukB = (lane >> 3) & 1;
    const int brow_in = (lane & 7) + ((lane >> 4) << 3);

    #pragma unroll 1
    for (int nb = 0; nb < 8; nb++) {
        float acc[2][4][4];
        #pragma unroll
        for (int mf = 0; mf < 2; mf++)
            #pragma unroll
            for (int j = 0; j < 4; j++)
                #pragma unroll
                for (int e = 0; e < 4; e++) acc[mf][j][e] = 0.f;

        // prefetch k-tile kt (128 bf16 cols = 256B/row) into stage st
        auto prefetch = [&](int kt, int st) {
            const int aoff = (kt & 1) * 128 + (kt >= 4 ? 256 : 0);
            const int boff = (kt & 1) * 128 + ((kt >= 2 && kt < 4) ? 256 : 0);
            const uint32_t abase = sb + SO_TILE + st * STAGEB;
            const uint32_t bbase = abase + 32768;
            #pragma unroll
            for (int i = 0; i < 8; i++) {
                int v = tid + TPB * i;
                if (v < 2048) {
                    int row = v >> 4, u = v & 15;
                    const void* src = g_A + (rowbase + row) * 512 + aoff + u * 8;
                    cp16(abase + row * 256 + ((u ^ ((row & 7) << 1)) << 4), src);
                } else {
                    int vb = v - 2048;
                    int nrow = vb >> 4, u = vb & 15;
                    const void* src = g_Bs + ((size_t)(c * KCB + nb * 128 + nrow)) * 512 + boff + u * 8;
                    cp16(bbase + nrow * 256 + ((u ^ ((nrow & 7) << 1)) << 4), src);
                }
            }
        };

        prefetch(0, 0); CP_COMMIT();
        prefetch(1, 1); CP_COMMIT();
        int st = 0;
        #pragma unroll 1
        for (int kt = 0; kt < NKT; kt++) {
            if (kt < NKT - 1) { CP_WAIT(1); } else { CP_WAIT(0); }
            __syncthreads();
            if (kt + 2 < NKT) {
                int st2 = st + 2; if (st2 >= 3) st2 -= 3;
                prefetch(kt + 2, st2); CP_COMMIT();
            }
            const uint32_t abase = sb + SO_TILE + st * STAGEB;
            const uint32_t bbase = abase + 32768;
            #pragma unroll
            for (int s = 0; s < 8; s++) {
                uint32_t a[2][4];
                #pragma unroll
                for (int mf = 0; mf < 2; mf++) {
                    int r = arow0 + mf * 16;
                    int u = s * 2 + ukA;
                    ldsm4(a[mf], abase + r * 256 + ((u ^ ((r & 7) << 1)) << 4));
                }
                uint32_t b[4][2];
                #pragma unroll
                for (int nf4 = 0; nf4 < 2; nf4++) {
                    int r = wc * 32 + nf4 * 16 + brow_in;
                    int u = s * 2 + ukB;
                    uint32_t t[4];
                    ldsm4(t, bbase + r * 256 + ((u ^ ((r & 7) << 1)) << 4));
                    b[nf4 * 2][0] = t[0]; b[nf4 * 2][1] = t[1];
                    b[nf4 * 2 + 1][0] = t[2]; b[nf4 * 2 + 1][1] = t[3];
                }
                #pragma unroll
                for (int mf = 0; mf < 2; mf++)
                    #pragma unroll
                    for (int j = 0; j < 4; j++)
                        mma16816(acc[mf][j], a[mf], b[j][0], b[j][1]);
            }
            if (++st >= 3) st -= 3;
        }

        // approx scores -> per-thread best-4 per row
        #pragma unroll
        for (int mf = 0; mf < 2; mf++) {
            #pragma unroll
            for (int h = 0; h < 2; h++) {
                const int ridx = mf * 2 + h;
                const float rrv = rrl[ridx];
                #pragma unroll
                for (int j = 0; j < 4; j++) {
                    #pragma unroll
                    for (int e = 0; e < 2; e++) {
                        int col = nb * 128 + wc * 32 + j * 8 + (lane & 3) * 2 + e;
                        float d2 = fmaf(-2.0f, acc[mf][j][h * 2 + e], rrv) + wws[col];
                        upd4(cv4 + ridx * 4, ci4 + ridx * 4, d2, col);
                    }
                }
            }
        }
    }
    __syncthreads();   // all MMA reads done before tile smem is reused

    // dump best-4 lists into (dead) tile smem: 128 rows x 64 slots
    float* cv = (float*)(smc + SO_TILE);
    int*   ci = (int*)(smc + SO_TILE + 32768);
    #pragma unroll
    for (int mf = 0; mf < 2; mf++)
        #pragma unroll
        for (int h = 0; h < 2; h++) {
            int row = wr * 32 + mf * 16 + g + 8 * h;
            int slot = wc * 16 + (lane & 3) * 4;
            #pragma unroll
            for (int s = 0; s < 4; s++) {
                cv[row * 64 + slot + s] = cv4[(mf * 2 + h) * 4 + s];
                ci[row * 64 + slot + s] = ci4[(mf * 2 + h) * 4 + s];
            }
        }
    __syncthreads();

    // exact rescore (reproduces the reference d2 pipeline bit-for-bit)
    if (tid < BM) {
        const float* cvr = cv + tid * 64;
        const int*   cir = ci + tid * 64;
        float mv = cvr[0];
        #pragma unroll
        for (int s = 1; s < 64; s++) mv = fminf(mv, cvr[s]);
        const float band = 1e-4f;

        const float* rp = resIn + (rowbase + tid) * DDIM;
        float q[4];
        #pragma unroll
        for (int qq = 0; qq < 4; qq++) {
            float s = 0.f;
            #pragma unroll
            for (int i = 0; i < 16; i++) {
                float4 v = *(const float4*)(rp + qq * 64 + i * 4);
                s = fmaf(v.x, v.x, s); s = fmaf(v.y, v.y, s);
                s = fmaf(v.z, v.z, s); s = fmaf(v.w, v.w, s);
            }
            q[qq] = s;
        }
        float rr = ((q[0] + q[1]) + q[2]) + q[3];

        float bv = 3.0e38f; int bi = 0x7fffffff;
        for (int s = 0; s < 64; s++) {
            if (cvr[s] <= mv + band) {
                int k = cir[s];
                const float* w = cbc + (size_t)k * DDIM;
                float acc = 0.f;
                #pragma unroll 8
                for (int i = 0; i < 64; i++) {
                    float4 rv = *(const float4*)(rp + i * 4);
                    float4 wv = *(const float4*)(w + i * 4);
                    acc = fmaf(rv.x, wv.x, acc); acc = fmaf(rv.y, wv.y, acc);
                    acc = fmaf(rv.z, wv.z, acc); acc = fmaf(rv.w, wv.w, acc);
                }
                float t  = fmaf(-2.0f, acc, rr);
                float d2 = t + wws[k];
                if (d2 < bv || (d2 == bv && k < bi)) { bv = d2; bi = k; }
            }
        }
        sIdx[tid] = bi;
        if (idxOut) idxOut[(rowbase + tid) * NCB + c] = (float)bi;
    }
    __syncthreads();

    // residual / quantized / loss / next-stage split (4 threads/row)
    float* lp = qs;
    {
        int row = tid >> 2, q = tid & 3;
        size_t grow = rowbase + row;
        const float* wrow = cbc + (size_t)sIdx[row] * DDIM;
        const float* rrow = resIn + grow * DDIM;
        float* ro = g_res + grow * DDIM;
        float* qo = qOut + grow * DDIM;
        __nv_bfloat16* a1o = g_A + grow * 512;
        __nv_bfloat16* a2o = a1o + 256;
        float lsum = 0.f;
        #pragma unroll
        for (int t = 0; t < 16; t++) {
            int d4 = q + 4 * t;   // interleaved for coalescing
            float4 w4 = *(const float4*)(wrow + d4 * 4);
            float4 r4 = *(const float4*)(rrow + d4 * 4);
            float4 nr;
            nr.x = r4.x - w4.x; nr.y = r4.y - w4.y;
            nr.z = r4.z - w4.z; nr.w = r4.w - w4.w;
            *(float4*)(ro + d4 * 4) = nr;
            float4 qv;
            if (c == 0) qv = w4;
            else {
                float4 qp = *(const float4*)(qo + d4 * 4);
                qv.x = qp.x + w4.x; qv.y = qp.y + w4.y;
                qv.z = qp.z + w4.z; qv.w = qp.w + w4.w;
            }
            *(float4*)(qo + d4 * 4) = qv;
            lsum = fmaf(nr.x, nr.x, lsum); lsum = fmaf(nr.y, nr.y, lsum);
            lsum = fmaf(nr.z, nr.z, lsum); lsum = fmaf(nr.w, nr.w, lsum);
            if (c < 7) {
                __nv_bfloat16 p1[4], p2[4];
                split2(nr.x, p1[0], p2[0]); split2(nr.y, p1[1], p2[1]);
                split2(nr.z, p1[2], p2[2]); split2(nr.w, p1[3], p2[3]);
                *(uint64_t*)(a1o + d4 * 4) = *(uint64_t*)p1;
                *(uint64_t*)(a2o + d4 * 4) = *(uint64_t*)p2;
            }
        }
        #pragma unroll
        for (int o = 16; o; o >>= 1) lsum += __shfl_down_sync(0xffffffffu, lsum, o);
        if (lane == 0) lp[warp] = lsum;
    }
    __syncthreads();
    if (tid == 0) {
        double s = 0.0;
        #pragma unroll
        for (int w = 0; w < 16; w++) s += (double)lp[w];
        g_lp[c * NBLOCKS + blockIdx.x] = s;
    }
}

__global__ void rvq_loss_kernel(float* __restrict__ out, int lossOff)
{
    if (lossOff < 0) return;
    __shared__ double sd[256];
    int tid = threadIdx.x;
    double s = 0.0;
    for (int i = tid; i < NCB * NBLOCKS; i += 256) s += g_lp[i];
    sd[tid] = s;
    __syncthreads();
    for (int o = 128; o; o >>= 1) {
        if (tid < o) sd[tid] += sd[tid + o];
        __syncthreads();
    }
    if (tid == 0) out[lossOff] = (float)(sd[0] / (double)((long long)NROWS * DDIM));
}

extern "C" void kernel_launch(void* const* d_in, const int* in_sizes, int n_in,
                              void* d_out, int out_size)
{
    const float* z  = (const float*)d_in[0];
    const float* cb = (const float*)d_in[1];
    float* out = (float*)d_out;

    static bool attr_set = false;
    if (!attr_set) {
        cudaFuncSetAttribute(rvq_stage_kernel,
                             cudaFuncAttributeMaxDynamicSharedMemorySize, SMEMB);
        attr_set = true;
    }

    const int NZ = NROWS * DDIM, NIDX = NROWS * NCB;
    float* idxOut = nullptr;
    int lossOff = -1;
    if (out_size >= NZ + NIDX + 1) { idxOut = out + NZ; lossOff = NZ + NIDX; }
    else if (out_size == NZ + NIDX) { idxOut = out + NZ; }
    else if (out_size == NZ + 1)    { lossOff = NZ; }

    rvq_splitA_kernel<<<NROWS * 64 / 256, 256>>>(z);
    rvq_splitB_kernel<<<NCB * KCB * 64 / 256, 256>>>(cb);
    rvq_ww_kernel<<<NCB * KCB / 8, 256>>>(cb);

    for (int c = 0; c < NCB; c++)
        rvq_stage_kernel<<<NBLOCKS, TPB, SMEMB>>>(z, cb, out, idxOut, c);

    rvq_loss_kernel<<<1, 256>>>(out, lossOff);
}

// round 8
// speedup vs baseline: 1.2948x; 1.2948x over previous
#include <cuda_runtime.h>
#include <cuda_bf16.h>
#include <cstdint>

#define NROWS 65536
#define DDIM  256
#define NCB   8
#define KCB   1024
#define BM    128
#define TPB   512
#define NBLOCKS (NROWS / BM)     // 512
#define NKT   4                  // 4 x 128 bf16 k-cols = K_ext 512 (2-term split)

// -------- device scratch --------
__device__ float         g_res[(size_t)NROWS * DDIM];        // 64 MB
__device__ __nv_bfloat16 g_A[(size_t)NROWS * 512];           // [row][a1(256)|a2(256)]
__device__ __nv_bfloat16 g_Bs[(size_t)NCB * KCB * 512];      // [ck][b1(256)|b2(256)] (b2 unused)
__device__ float         g_ww[NCB * KCB];
__device__ double        g_lp[NCB * NBLOCKS];

// -------- smem layout (bytes) --------
#define SO_SIDX 0        // 128 int
#define SO_RR   512      // 128 f
#define SO_QS   1024     // 512 f (reused as lp)
#define SO_WW   4096     // 1024 f
#define SO_TILE 8192     // 3 stages x (A 32KB + B 32KB); reused as cand arrays
#define STAGEB  65536
#define SMEMB   (SO_TILE + 3 * STAGEB)   // 204800

__device__ __forceinline__ uint32_t smem_u32(const void* p) {
    uint32_t a;
    asm("{ .reg .u64 t; cvta.to.shared.u64 t, %1; cvt.u32.u64 %0, t; }" : "=r"(a) : "l"(p));
    return a;
}
__device__ __forceinline__ void cp16(uint32_t dst, const void* src) {
    asm volatile("cp.async.cg.shared.global [%0], [%1], 16;" :: "r"(dst), "l"(src));
}
#define CP_COMMIT() asm volatile("cp.async.commit_group;" ::: "memory")
#define CP_WAIT(n)  asm volatile("cp.async.wait_group %0;" :: "n"(n) : "memory")

__device__ __forceinline__ void ldsm4(uint32_t* r, uint32_t addr) {
    asm volatile("ldmatrix.sync.aligned.m8n8.x4.shared.b16 {%0,%1,%2,%3}, [%4];"
        : "=r"(r[0]), "=r"(r[1]), "=r"(r[2]), "=r"(r[3]) : "r"(addr));
}
__device__ __forceinline__ void mma16816(float* d, const uint32_t* a, uint32_t b0, uint32_t b1) {
    asm volatile(
        "mma.sync.aligned.m16n8k16.row.col.f32.bf16.bf16.f32 "
        "{%0,%1,%2,%3}, {%4,%5,%6,%7}, {%8,%9}, {%0,%1,%2,%3};"
        : "+f"(d[0]), "+f"(d[1]), "+f"(d[2]), "+f"(d[3])
        : "r"(a[0]), "r"(a[1]), "r"(a[2]), "r"(a[3]), "r"(b0), "r"(b1));
}
__device__ __forceinline__ void split2(float x, __nv_bfloat16& p1, __nv_bfloat16& p2) {
    p1 = __float2bfloat16_rn(x);
    p2 = __float2bfloat16_rn(x - __bfloat162float(p1));
}
// keep sorted-ascending best-4 (lexicographic on (val, idx))
__device__ __forceinline__ void upd4(float* v, int* ix, float nv, int ni) {
    if (nv > v[3] || (nv == v[3] && ni > ix[3])) return;
    v[3] = nv; ix[3] = ni;
    #pragma unroll
    for (int p = 3; p > 0; p--) {
        bool sw = (v[p] < v[p-1]) || (v[p] == v[p-1] && ix[p] < ix[p-1]);
        if (sw) {
            float tv = v[p]; v[p] = v[p-1]; v[p-1] = tv;
            int   ti = ix[p]; ix[p] = ix[p-1]; ix[p-1] = ti;
        }
    }
}

// ---- prep kernels ----
__global__ void rvq_splitA_kernel(const float* __restrict__ z)
{
    int id = blockIdx.x * 256 + threadIdx.x;
    int row = id >> 6, d4 = id & 63;
    float4 v = *(const float4*)(z + (size_t)row * DDIM + d4 * 4);
    __nv_bfloat16 p1[4], p2[4];
    split2(v.x, p1[0], p2[0]); split2(v.y, p1[1], p2[1]);
    split2(v.z, p1[2], p2[2]); split2(v.w, p1[3], p2[3]);
    __nv_bfloat16* a = g_A + (size_t)row * 512 + d4 * 4;
    *(uint64_t*)(a)       = *(uint64_t*)p1;
    *(uint64_t*)(a + 256) = *(uint64_t*)p2;
}
__global__ void rvq_splitB_kernel(const float* __restrict__ cb)
{
    int id = blockIdx.x * 256 + threadIdx.x;
    int ck = id >> 6, d4 = id & 63;
    float4 v = *(const float4*)(cb + (size_t)ck * DDIM + d4 * 4);
    __nv_bfloat16 p1[4], p2[4];
    split2(v.x, p1[0], p2[0]); split2(v.y, p1[1], p2[1]);
    split2(v.z, p1[2], p2[2]); split2(v.w, p1[3], p2[3]);
    __nv_bfloat16* b = g_Bs + (size_t)ck * 512 + d4 * 4;
    *(uint64_t*)(b)       = *(uint64_t*)p1;
    *(uint64_t*)(b + 256) = *(uint64_t*)p2;
}
__global__ void rvq_ww_kernel(const float* __restrict__ cb)
{
    const int warp = threadIdx.x >> 5, lane = threadIdx.x & 31;
    const int k = blockIdx.x * 8 + warp;
    const float* w = cb + (size_t)k * DDIM;
    float s = 0.f;
    #pragma unroll
    for (int t = 0; t < 8; t++) { float v = w[lane + 32 * t]; s = fmaf(v, v, s); }
    #pragma unroll
    for (int o = 16; o; o >>= 1) s += __shfl_down_sync(0xffffffffu, s, o);
    if (lane == 0) g_ww[k] = s;
}

// ---- fused HMMA stage: approx GEMM filter + exact rescore ----
__global__ void __launch_bounds__(TPB)
rvq_stage_kernel(const float* __restrict__ z, const float* __restrict__ cb,
                 float* __restrict__ qOut, float* __restrict__ idxOut, int c)
{
    extern __shared__ char smc[];
    const uint32_t sb = smem_u32(smc);
    int*   sIdx = (int*)(smc + SO_SIDX);
    float* rrsh = (float*)(smc + SO_RR);
    float* qs   = (float*)(smc + SO_QS);
    float* wws  = (float*)(smc + SO_WW);

    const int tid  = threadIdx.x;
    const int lane = tid & 31;
    const int warp = tid >> 5;
    const int wr   = warp >> 2;      // 0..3 (32-row slice)
    const int wc   = warp & 3;       // 0..3 (32-col slice)
    const size_t rowbase = (size_t)blockIdx.x * BM;
    const float* resIn = (c == 0) ? z : g_res;
    const float* cbc = cb + (size_t)c * KCB * DDIM;

    for (int i = tid; i < KCB; i += TPB) wws[i] = g_ww[c * KCB + i];

    // approx rr per row (4 threads/row) — only feeds the filter
    {
        int row = tid >> 2, q = tid & 3;
        const float* rp = resIn + (rowbase + row) * DDIM + q * 64;
        float s = 0.f;
        #pragma unroll
        for (int i = 0; i < 16; i++) {
            float4 v = *(const float4*)(rp + i * 4);
            s = fmaf(v.x, v.x, s); s = fmaf(v.y, v.y, s);
            s = fmaf(v.z, v.z, s); s = fmaf(v.w, v.w, s);
        }
        qs[tid] = s;
    }
    __syncthreads();
    if (tid < BM)
        rrsh[tid] = qs[tid * 4] + qs[tid * 4 + 1] + qs[tid * 4 + 2] + qs[tid * 4 + 3];
    __syncthreads();

    const int g = lane >> 2;
    float rrl[4];
    #pragma unroll
    for (int mf = 0; mf < 2; mf++)
        #pragma unroll
        for (int h = 0; h < 2; h++)
            rrl[mf * 2 + h] = rrsh[wr * 32 + mf * 16 + g + 8 * h];

    // per-thread best-4 per owned row (4 rows/thread)
    float cv4[16]; int ci4[16];
    #pragma unroll
    for (int i = 0; i < 16; i++) { cv4[i] = 3.0e38f; ci4[i] = 0x7fffffff; }

    const int arow0 = wr * 32 + (lane & 15);
    const int ukA = lane >> 4;
    const int ukB = (lane >> 3) & 1;
    const int brow_in = (lane & 7) + ((lane >> 4) << 3);

    #pragma unroll 1
    for (int nb = 0; nb < 8; nb++) {
        float acc[2][4][4];
        #pragma unroll
        for (int mf = 0; mf < 2; mf++)
            #pragma unroll
            for (int j = 0; j < 4; j++)
                #pragma unroll
                for (int e = 0; e < 4; e++) acc[mf][j][e] = 0.f;

        // prefetch k-tile kt (128 bf16 cols = 256B/row) into stage st
        // 2-term: A covers [a1|a2] (aoff = kt*128), B repeats b1 (boff = (kt&1)*128)
        auto prefetch = [&](int kt, int st) {
            const int aoff = kt * 128;
            const int boff = (kt & 1) * 128;
            const uint32_t abase = sb + SO_TILE + st * STAGEB;
            const uint32_t bbase = abase + 32768;
            #pragma unroll
            for (int i = 0; i < 8; i++) {
                int v = tid + TPB * i;
                if (v < 2048) {
                    int row = v >> 4, u = v & 15;
                    const void* src = g_A + (rowbase + row) * 512 + aoff + u * 8;
                    cp16(abase + row * 256 + ((u ^ (row & 7)) << 4), src);
                } else {
                    int vb = v - 2048;
                    int nrow = vb >> 4, u = vb & 15;
                    const void* src = g_Bs + ((size_t)(c * KCB + nb * 128 + nrow)) * 512 + boff + u * 8;
                    cp16(bbase + nrow * 256 + ((u ^ (nrow & 7)) << 4), src);
                }
            }
        };

        prefetch(0, 0); CP_COMMIT();
        prefetch(1, 1); CP_COMMIT();
        int st = 0;
        #pragma unroll 1
        for (int kt = 0; kt < NKT; kt++) {
            if (kt < NKT - 1) { CP_WAIT(1); } else { CP_WAIT(0); }
            __syncthreads();
            if (kt + 2 < NKT) {
                int st2 = st + 2; if (st2 >= 3) st2 -= 3;
                prefetch(kt + 2, st2); CP_COMMIT();
            }
            const uint32_t abase = sb + SO_TILE + st * STAGEB;
            const uint32_t bbase = abase + 32768;
            #pragma unroll
            for (int s = 0; s < 8; s++) {
                uint32_t a[2][4];
                #pragma unroll
                for (int mf = 0; mf < 2; mf++) {
                    int r = arow0 + mf * 16;
                    int u = s * 2 + ukA;
                    ldsm4(a[mf], abase + r * 256 + ((u ^ (r & 7)) << 4));
                }
                uint32_t b[4][2];
                #pragma unroll
                for (int nf4 = 0; nf4 < 2; nf4++) {
                    int r = wc * 32 + nf4 * 16 + brow_in;
                    int u = s * 2 + ukB;
                    uint32_t t[4];
                    ldsm4(t, bbase + r * 256 + ((u ^ (r & 7)) << 4));
                    b[nf4 * 2][0] = t[0]; b[nf4 * 2][1] = t[1];
                    b[nf4 * 2 + 1][0] = t[2]; b[nf4 * 2 + 1][1] = t[3];
                }
                #pragma unroll
                for (int mf = 0; mf < 2; mf++)
                    #pragma unroll
                    for (int j = 0; j < 4; j++)
                        mma16816(acc[mf][j], a[mf], b[j][0], b[j][1]);
            }
            if (++st >= 3) st -= 3;
        }

        // approx scores -> per-thread best-4 per row
        #pragma unroll
        for (int mf = 0; mf < 2; mf++) {
            #pragma unroll
            for (int h = 0; h < 2; h++) {
                const int ridx = mf * 2 + h;
                const float rrv = rrl[ridx];
                #pragma unroll
                for (int j = 0; j < 4; j++) {
                    #pragma unroll
                    for (int e = 0; e < 2; e++) {
                        int col = nb * 128 + wc * 32 + j * 8 + (lane & 3) * 2 + e;
                        float d2 = fmaf(-2.0f, acc[mf][j][h * 2 + e], rrv) + wws[col];
                        upd4(cv4 + ridx * 4, ci4 + ridx * 4, d2, col);
                    }
                }
            }
        }
    }
    __syncthreads();   // all MMA reads done before tile smem is reused

    // dump best-4 lists into (dead) tile smem: 128 rows x 64 slots
    float* cv = (float*)(smc + SO_TILE);
    int*   ci = (int*)(smc + SO_TILE + 32768);
    #pragma unroll
    for (int mf = 0; mf < 2; mf++)
        #pragma unroll
        for (int h = 0; h < 2; h++) {
            int row = wr * 32 + mf * 16 + g + 8 * h;
            int slot = wc * 16 + (lane & 3) * 4;
            #pragma unroll
            for (int s = 0; s < 4; s++) {
                cv[row * 64 + slot + s] = cv4[(mf * 2 + h) * 4 + s];
                ci[row * 64 + slot + s] = ci4[(mf * 2 + h) * 4 + s];
            }
        }
    __syncthreads();

    // exact rescore (reproduces the reference d2 pipeline bit-for-bit)
    if (tid < BM) {
        const float* cvr = cv + tid * 64;
        const int*   cir = ci + tid * 64;
        float mv = cvr[0];
        #pragma unroll
        for (int s = 1; s < 64; s++) mv = fminf(mv, cvr[s]);
        const float band = 4e-3f;   // >= 2x worst-case 2-term approx error

        const float* rp = resIn + (rowbase + tid) * DDIM;
        float q[4];
        #pragma unroll
        for (int qq = 0; qq < 4; qq++) {
            float s = 0.f;
            #pragma unroll
            for (int i = 0; i < 16; i++) {
                float4 v = *(const float4*)(rp + qq * 64 + i * 4);
                s = fmaf(v.x, v.x, s); s = fmaf(v.y, v.y, s);
                s = fmaf(v.z, v.z, s); s = fmaf(v.w, v.w, s);
            }
            q[qq] = s;
        }
        float rr = ((q[0] + q[1]) + q[2]) + q[3];

        float bv = 3.0e38f; int bi = 0x7fffffff;
        for (int s = 0; s < 64; s++) {
            if (cvr[s] <= mv + band) {
                int k = cir[s];
                const float* w = cbc + (size_t)k * DDIM;
                float acc = 0.f;
                #pragma unroll 8
                for (int i = 0; i < 64; i++) {
                    float4 rv = *(const float4*)(rp + i * 4);
                    float4 wv = *(const float4*)(w + i * 4);
                    acc = fmaf(rv.x, wv.x, acc); acc = fmaf(rv.y, wv.y, acc);
                    acc = fmaf(rv.z, wv.z, acc); acc = fmaf(rv.w, wv.w, acc);
                }
                float t  = fmaf(-2.0f, acc, rr);
                float d2 = t + wws[k];
                if (d2 < bv || (d2 == bv && k < bi)) { bv = d2; bi = k; }
            }
        }
        sIdx[tid] = bi;
        if (idxOut) idxOut[(rowbase + tid) * NCB + c] = (float)bi;
    }
    __syncthreads();

    // residual / quantized / loss / next-stage split (4 threads/row)
    float* lp = qs;
    {
        int row = tid >> 2, q = tid & 3;
        size_t grow = rowbase + row;
        const float* wrow = cbc + (size_t)sIdx[row] * DDIM;
        const float* rrow = resIn + grow * DDIM;
        float* ro = g_res + grow * DDIM;
        float* qo = qOut + grow * DDIM;
        __nv_bfloat16* a1o = g_A + grow * 512;
        __nv_bfloat16* a2o = a1o + 256;
        float lsum = 0.f;
        #pragma unroll
        for (int t = 0; t < 16; t++) {
            int d4 = q + 4 * t;   // interleaved for coalescing
            float4 w4 = *(const float4*)(wrow + d4 * 4);
            float4 r4 = *(const float4*)(rrow + d4 * 4);
            float4 nr;
            nr.x = r4.x - w4.x; nr.y = r4.y - w4.y;
            nr.z = r4.z - w4.z; nr.w = r4.w - w4.w;
            *(float4*)(ro + d4 * 4) = nr;
            float4 qv;
            if (c == 0) qv = w4;
            else {
                float4 qp = *(const float4*)(qo + d4 * 4);
                qv.x = qp.x + w4.x; qv.y = qp.y + w4.y;
                qv.z = qp.z + w4.z; qv.w = qp.w + w4.w;
            }
            *(float4*)(qo + d4 * 4) = qv;
            lsum = fmaf(nr.x, nr.x, lsum); lsum = fmaf(nr.y, nr.y, lsum);
            lsum = fmaf(nr.z, nr.z, lsum); lsum = fmaf(nr.w, nr.w, lsum);
            if (c < 7) {
                __nv_bfloat16 p1[4], p2[4];
                split2(nr.x, p1[0], p2[0]); split2(nr.y, p1[1], p2[1]);
                split2(nr.z, p1[2], p2[2]); split2(nr.w, p1[3], p2[3]);
                *(uint64_t*)(a1o + d4 * 4) = *(uint64_t*)p1;
                *(uint64_t*)(a2o + d4 * 4) = *(uint64_t*)p2;
            }
        }
        #pragma unroll
        for (int o = 16; o; o >>= 1) lsum += __shfl_down_sync(0xffffffffu, lsum, o);
        if (lane == 0) lp[warp] = lsum;
    }
    __syncthreads();
    if (tid == 0) {
        double s = 0.0;
        #pragma unroll
        for (int w = 0; w < 16; w++) s += (double)lp[w];
        g_lp[c * NBLOCKS + blockIdx.x] = s;
    }
}

__global__ void rvq_loss_kernel(float* __restrict__ out, int lossOff)
{
    if (lossOff < 0) return;
    __shared__ double sd[256];
    int tid = threadIdx.x;
    double s = 0.0;
    for (int i = tid; i < NCB * NBLOCKS; i += 256) s += g_lp[i];
    sd[tid] = s;
    __syncthreads();
    for (int o = 128; o; o >>= 1) {
        if (tid < o) sd[tid] += sd[tid + o];
        __syncthreads();
    }
    if (tid == 0) out[lossOff] = (float)(sd[0] / (double)((long long)NROWS * DDIM));
}

extern "C" void kernel_launch(void* const* d_in, const int* in_sizes, int n_in,
                              void* d_out, int out_size)
{
    const float* z  = (const float*)d_in[0];
    const float* cb = (const float*)d_in[1];
    float* out = (float*)d_out;

    static bool attr_set = false;
    if (!attr_set) {
        cudaFuncSetAttribute(rvq_stage_kernel,
                             cudaFuncAttributeMaxDynamicSharedMemorySize, SMEMB);
        attr_set = true;
    }

    const int NZ = NROWS * DDIM, NIDX = NROWS * NCB;
    float* idxOut = nullptr;
    int lossOff = -1;
    if (out_size >= NZ + NIDX + 1) { idxOut = out + NZ; lossOff = NZ + NIDX; }
    else if (out_size == NZ + NIDX) { idxOut = out + NZ; }
    else if (out_size == NZ + 1)    { lossOff = NZ; }

    rvq_splitA_kernel<<<NROWS * 64 / 256, 256>>>(z);
    rvq_splitB_kernel<<<NCB * KCB * 64 / 256, 256>>>(cb);
    rvq_ww_kernel<<<NCB * KCB / 8, 256>>>(cb);

    for (int c = 0; c < NCB; c++)
        rvq_stage_kernel<<<NBLOCKS, TPB, SMEMB>>>(z, cb, out, idxOut, c);

    rvq_loss_kernel<<<1, 256>>>(out, lossOff);
}

// round 9
// speedup vs baseline: 1.5642x; 1.2080x over previous
#include <cuda_runtime.h>
#include <cuda_bf16.h>
#include <cstdint>

#define NROWS 65536
#define DDIM  256
#define NCB   8
#define KCB   1024
#define BM    128
#define TPB   512
#define NBLOCKS (NROWS / BM)     // 512
#define NKTI  16                 // 8 nb x 2 k-tiles (K_ext 256, 1-term filter)

// -------- device scratch --------
__device__ float         g_res[(size_t)NROWS * DDIM];        // 64 MB
__device__ __nv_bfloat16 g_A1[(size_t)NROWS * 256];          // bf16(residual), compact
__device__ __nv_bfloat16 g_B1[(size_t)NCB * KCB * 256];      // bf16(codebooks), compact
__device__ float         g_ww[NCB * KCB];
__device__ double        g_lp[NCB * NBLOCKS];

// -------- smem layout (bytes) --------
#define SO_SIDX 0        // 128 int
#define SO_RR   512      // 128 f
#define SO_QS   1024     // 512 f (reused as lp)
#define SO_WW   4096     // 1024 f
#define SO_TILE 8192     // 3 stages x (A 32KB + B 32KB); reused as cand arrays
#define STAGEB  65536
#define SMEMB   (SO_TILE + 3 * STAGEB)   // 204800

__device__ __forceinline__ uint32_t smem_u32(const void* p) {
    uint32_t a;
    asm("{ .reg .u64 t; cvta.to.shared.u64 t, %1; cvt.u32.u64 %0, t; }" : "=r"(a) : "l"(p));
    return a;
}
__device__ __forceinline__ void cp16(uint32_t dst, const void* src) {
    asm volatile("cp.async.cg.shared.global [%0], [%1], 16;" :: "r"(dst), "l"(src));
}
#define CP_COMMIT() asm volatile("cp.async.commit_group;" ::: "memory")
#define CP_WAIT(n)  asm volatile("cp.async.wait_group %0;" :: "n"(n) : "memory")

__device__ __forceinline__ void ldsm4(uint32_t* r, uint32_t addr) {
    asm volatile("ldmatrix.sync.aligned.m8n8.x4.shared.b16 {%0,%1,%2,%3}, [%4];"
        : "=r"(r[0]), "=r"(r[1]), "=r"(r[2]), "=r"(r[3]) : "r"(addr));
}
__device__ __forceinline__ void mma16816(float* d, const uint32_t* a, uint32_t b0, uint32_t b1) {
    asm volatile(
        "mma.sync.aligned.m16n8k16.row.col.f32.bf16.bf16.f32 "
        "{%0,%1,%2,%3}, {%4,%5,%6,%7}, {%8,%9}, {%0,%1,%2,%3};"
        : "+f"(d[0]), "+f"(d[1]), "+f"(d[2]), "+f"(d[3])
        : "r"(a[0]), "r"(a[1]), "r"(a[2]), "r"(a[3]), "r"(b0), "r"(b1));
}
// keep sorted-ascending best-4 (lexicographic on (val, idx))
__device__ __forceinline__ void upd4(float* v, int* ix, float nv, int ni) {
    if (nv > v[3] || (nv == v[3] && ni > ix[3])) return;
    v[3] = nv; ix[3] = ni;
    #pragma unroll
    for (int p = 3; p > 0; p--) {
        bool sw = (v[p] < v[p-1]) || (v[p] == v[p-1] && ix[p] < ix[p-1]);
        if (sw) {
            float tv = v[p]; v[p] = v[p-1]; v[p-1] = tv;
            int   ti = ix[p]; ix[p] = ix[p-1]; ix[p-1] = ti;
        }
    }
}

// ---- prep kernels ----
__global__ void rvq_splitA_kernel(const float* __restrict__ z)
{
    int id = blockIdx.x * 256 + threadIdx.x;
    int row = id >> 6, d4 = id & 63;
    float4 v = *(const float4*)(z + (size_t)row * DDIM + d4 * 4);
    __nv_bfloat16 p1[4];
    p1[0] = __float2bfloat16_rn(v.x); p1[1] = __float2bfloat16_rn(v.y);
    p1[2] = __float2bfloat16_rn(v.z); p1[3] = __float2bfloat16_rn(v.w);
    *(uint64_t*)(g_A1 + (size_t)row * 256 + d4 * 4) = *(uint64_t*)p1;
}
__global__ void rvq_splitB_kernel(const float* __restrict__ cb)
{
    int id = blockIdx.x * 256 + threadIdx.x;
    int ck = id >> 6, d4 = id & 63;
    float4 v = *(const float4*)(cb + (size_t)ck * DDIM + d4 * 4);
    __nv_bfloat16 p1[4];
    p1[0] = __float2bfloat16_rn(v.x); p1[1] = __float2bfloat16_rn(v.y);
    p1[2] = __float2bfloat16_rn(v.z); p1[3] = __float2bfloat16_rn(v.w);
    *(uint64_t*)(g_B1 + (size_t)ck * 256 + d4 * 4) = *(uint64_t*)p1;
}
__global__ void rvq_ww_kernel(const float* __restrict__ cb)
{
    const int warp = threadIdx.x >> 5, lane = threadIdx.x & 31;
    const int k = blockIdx.x * 8 + warp;
    const float* w = cb + (size_t)k * DDIM;
    float s = 0.f;
    #pragma unroll
    for (int t = 0; t < 8; t++) { float v = w[lane + 32 * t]; s = fmaf(v, v, s); }
    #pragma unroll
    for (int o = 16; o; o >>= 1) s += __shfl_down_sync(0xffffffffu, s, o);
    if (lane == 0) g_ww[k] = s;
}

// ---- fused HMMA stage: 1-term bf16 filter + exact rescore ----
__global__ void __launch_bounds__(TPB)
rvq_stage_kernel(const float* __restrict__ z, const float* __restrict__ cb,
                 float* __restrict__ qOut, float* __restrict__ idxOut, int c)
{
    extern __shared__ char smc[];
    const uint32_t sb = smem_u32(smc);
    int*   sIdx = (int*)(smc + SO_SIDX);
    float* rrsh = (float*)(smc + SO_RR);
    float* qs   = (float*)(smc + SO_QS);
    float* wws  = (float*)(smc + SO_WW);

    const int tid  = threadIdx.x;
    const int lane = tid & 31;
    const int warp = tid >> 5;
    const int wr   = warp >> 2;      // 0..3 (32-row slice)
    const int wc   = warp & 3;       // 0..3 (32-col slice)
    const size_t rowbase = (size_t)blockIdx.x * BM;
    const float* resIn = (c == 0) ? z : g_res;
    const float* cbc = cb + (size_t)c * KCB * DDIM;

    for (int i = tid; i < KCB; i += TPB) wws[i] = g_ww[c * KCB + i];

    // approx rr per row (4 threads/row) — only feeds the filter
    {
        int row = tid >> 2, q = tid & 3;
        const float* rp = resIn + (rowbase + row) * DDIM + q * 64;
        float s = 0.f;
        #pragma unroll
        for (int i = 0; i < 16; i++) {
            float4 v = *(const float4*)(rp + i * 4);
            s = fmaf(v.x, v.x, s); s = fmaf(v.y, v.y, s);
            s = fmaf(v.z, v.z, s); s = fmaf(v.w, v.w, s);
        }
        qs[tid] = s;
    }
    __syncthreads();
    if (tid < BM)
        rrsh[tid] = qs[tid * 4] + qs[tid * 4 + 1] + qs[tid * 4 + 2] + qs[tid * 4 + 3];
    __syncthreads();

    const int g = lane >> 2;
    float rrl[4];
    #pragma unroll
    for (int mf = 0; mf < 2; mf++)
        #pragma unroll
        for (int h = 0; h < 2; h++)
            rrl[mf * 2 + h] = rrsh[wr * 32 + mf * 16 + g + 8 * h];

    // per-thread best-4 per owned row (4 rows/thread)
    float cv4[16]; int ci4[16];
    #pragma unroll
    for (int i = 0; i < 16; i++) { cv4[i] = 3.0e38f; ci4[i] = 0x7fffffff; }

    const int arow0 = wr * 32 + (lane & 15);
    const int ukA = lane >> 4;
    const int ukB = (lane >> 3) & 1;
    const int brow_in = (lane & 7) + ((lane >> 4) << 3);

    float acc[2][4][4];

    // prefetch k-tile for flattened index kti (nb = kti>>1, kt = kti&1) into stage st
    auto prefetch = [&](int kti_t, int st) {
        const int nb_t = kti_t >> 1;
        const int off  = (kti_t & 1) * 128;   // which 128-col half of the 256-col rows
        const uint32_t abase = sb + SO_TILE + st * STAGEB;
        const uint32_t bbase = abase + 32768;
        #pragma unroll
        for (int i = 0; i < 4; i++) {         // A: 2048 16B units
            int v = tid + TPB * i;
            int row = v >> 4, u = v & 15;
            const void* src = g_A1 + (rowbase + row) * 256 + off + u * 8;
            cp16(abase + row * 256 + ((u ^ (row & 7)) << 4), src);
        }
        #pragma unroll
        for (int i = 0; i < 4; i++) {         // B: 2048 16B units
            int v = tid + TPB * i;
            int nrow = v >> 4, u = v & 15;
            const void* src = g_B1 + ((size_t)(c * KCB + nb_t * 128 + nrow)) * 256 + off + u * 8;
            cp16(bbase + nrow * 256 + ((u ^ (nrow & 7)) << 4), src);
        }
    };

    prefetch(0, 0); CP_COMMIT();
    prefetch(1, 1); CP_COMMIT();
    #pragma unroll 1
    for (int kti = 0; kti < NKTI; kti++) {
        if (kti < NKTI - 1) { CP_WAIT(1); } else { CP_WAIT(0); }
        __syncthreads();
        if (kti + 2 < NKTI) {
            int st2 = (kti + 2) % 3;
            prefetch(kti + 2, st2); CP_COMMIT();
        }
        const int nb = kti >> 1, kt = kti & 1;
        if (kt == 0) {
            #pragma unroll
            for (int mf = 0; mf < 2; mf++)
                #pragma unroll
                for (int j = 0; j < 4; j++)
                    #pragma unroll
                    for (int e = 0; e < 4; e++) acc[mf][j][e] = 0.f;
        }
        const uint32_t abase = sb + SO_TILE + (kti % 3) * STAGEB;
        const uint32_t bbase = abase + 32768;
        #pragma unroll
        for (int s = 0; s < 8; s++) {
            uint32_t a[2][4];
            #pragma unroll
            for (int mf = 0; mf < 2; mf++) {
                int r = arow0 + mf * 16;
                int u = s * 2 + ukA;
                ldsm4(a[mf], abase + r * 256 + ((u ^ (r & 7)) << 4));
            }
            uint32_t b[4][2];
            #pragma unroll
            for (int nf4 = 0; nf4 < 2; nf4++) {
                int r = wc * 32 + nf4 * 16 + brow_in;
                int u = s * 2 + ukB;
                uint32_t t[4];
                ldsm4(t, bbase + r * 256 + ((u ^ (r & 7)) << 4));
                b[nf4 * 2][0] = t[0]; b[nf4 * 2][1] = t[1];
                b[nf4 * 2 + 1][0] = t[2]; b[nf4 * 2 + 1][1] = t[3];
            }
            #pragma unroll
            for (int mf = 0; mf < 2; mf++)
                #pragma unroll
                for (int j = 0; j < 4; j++)
                    mma16816(acc[mf][j], a[mf], b[j][0], b[j][1]);
        }
        if (kt == 1) {
            // approx scores -> per-thread best-4 per row
            #pragma unroll
            for (int mf = 0; mf < 2; mf++) {
                #pragma unroll
                for (int h = 0; h < 2; h++) {
                    const int ridx = mf * 2 + h;
                    const float rrv = rrl[ridx];
                    #pragma unroll
                    for (int j = 0; j < 4; j++) {
                        #pragma unroll
                        for (int e = 0; e < 2; e++) {
                            int col = nb * 128 + wc * 32 + j * 8 + (lane & 3) * 2 + e;
                            float d2 = fmaf(-2.0f, acc[mf][j][h * 2 + e], rrv) + wws[col];
                            upd4(cv4 + ridx * 4, ci4 + ridx * 4, d2, col);
                        }
                    }
                }
            }
        }
    }
    __syncthreads();   // all MMA reads done before tile smem is reused

    // dump best-4 lists into (dead) tile smem: 128 rows x 64 slots
    float* cv = (float*)(smc + SO_TILE);
    int*   ci = (int*)(smc + SO_TILE + 32768);
    #pragma unroll
    for (int mf = 0; mf < 2; mf++)
        #pragma unroll
        for (int h = 0; h < 2; h++) {
            int row = wr * 32 + mf * 16 + g + 8 * h;
            int slot = wc * 16 + (lane & 3) * 4;
            #pragma unroll
            for (int s = 0; s < 4; s++) {
                cv[row * 64 + slot + s] = cv4[(mf * 2 + h) * 4 + s];
                ci[row * 64 + slot + s] = ci4[(mf * 2 + h) * 4 + s];
            }
        }
    __syncthreads();

    // exact rescore (reproduces the reference d2 pipeline bit-for-bit)
    if (tid < BM) {
        const float* cvr = cv + tid * 64;
        const int*   cir = ci + tid * 64;
        float mv = cvr[0];
        #pragma unroll
        for (int s = 1; s < 64; s++) mv = fminf(mv, cvr[s]);
        const float band = 3e-3f;   // >= 3x worst-case 1-term bf16 error (9.8e-4)

        const float* rp = resIn + (rowbase + tid) * DDIM;
        float q[4];
        #pragma unroll
        for (int qq = 0; qq < 4; qq++) {
            float s = 0.f;
            #pragma unroll
            for (int i = 0; i < 16; i++) {
                float4 v = *(const float4*)(rp + qq * 64 + i * 4);
                s = fmaf(v.x, v.x, s); s = fmaf(v.y, v.y, s);
                s = fmaf(v.z, v.z, s); s = fmaf(v.w, v.w, s);
            }
            q[qq] = s;
        }
        float rr = ((q[0] + q[1]) + q[2]) + q[3];

        float bv = 3.0e38f; int bi = 0x7fffffff;
        for (int s = 0; s < 64; s++) {
            if (cvr[s] <= mv + band) {
                int k = cir[s];
                const float* w = cbc + (size_t)k * DDIM;
                float acc2 = 0.f;
                #pragma unroll 8
                for (int i = 0; i < 64; i++) {
                    float4 rv = *(const float4*)(rp + i * 4);
                    float4 wv = *(const float4*)(w + i * 4);
                    acc2 = fmaf(rv.x, wv.x, acc2); acc2 = fmaf(rv.y, wv.y, acc2);
                    acc2 = fmaf(rv.z, wv.z, acc2); acc2 = fmaf(rv.w, wv.w, acc2);
                }
                float t  = fmaf(-2.0f, acc2, rr);
                float d2 = t + wws[k];
                if (d2 < bv || (d2 == bv && k < bi)) { bv = d2; bi = k; }
            }
        }
        sIdx[tid] = bi;
        if (idxOut) idxOut[(rowbase + tid) * NCB + c] = (float)bi;
    }
    __syncthreads();

    // residual / quantized / loss / next-stage bf16 (4 threads/row)
    float* lp = qs;
    {
        int row = tid >> 2, q = tid & 3;
        size_t grow = rowbase + row;
        const float* wrow = cbc + (size_t)sIdx[row] * DDIM;
        const float* rrow = resIn + grow * DDIM;
        float* ro = g_res + grow * DDIM;
        float* qo = qOut + grow * DDIM;
        __nv_bfloat16* a1o = g_A1 + grow * 256;
        float lsum = 0.f;
        #pragma unroll
        for (int t = 0; t < 16; t++) {
            int d4 = q + 4 * t;   // interleaved for coalescing
            float4 w4 = *(const float4*)(wrow + d4 * 4);
            float4 r4 = *(const float4*)(rrow + d4 * 4);
            float4 nr;
            nr.x = r4.x - w4.x; nr.y = r4.y - w4.y;
            nr.z = r4.z - w4.z; nr.w = r4.w - w4.w;
            *(float4*)(ro + d4 * 4) = nr;
            float4 qv;
            if (c == 0) qv = w4;
            else {
                float4 qp = *(const float4*)(qo + d4 * 4);
                qv.x = qp.x + w4.x; qv.y = qp.y + w4.y;
                qv.z = qp.z + w4.z; qv.w = qp.w + w4.w;
            }
            *(float4*)(qo + d4 * 4) = qv;
            lsum = fmaf(nr.x, nr.x, lsum); lsum = fmaf(nr.y, nr.y, lsum);
            lsum = fmaf(nr.z, nr.z, lsum); lsum = fmaf(nr.w, nr.w, lsum);
            if (c < 7) {
                __nv_bfloat16 p1[4];
                p1[0] = __float2bfloat16_rn(nr.x); p1[1] = __float2bfloat16_rn(nr.y);
                p1[2] = __float2bfloat16_rn(nr.z); p1[3] = __float2bfloat16_rn(nr.w);
                *(uint64_t*)(a1o + d4 * 4) = *(uint64_t*)p1;
            }
        }
        #pragma unroll
        for (int o = 16; o; o >>= 1) lsum += __shfl_down_sync(0xffffffffu, lsum, o);
        if (lane == 0) lp[warp] = lsum;
    }
    __syncthreads();
    if (tid == 0) {
        double s = 0.0;
        #pragma unroll
        for (int w = 0; w < 16; w++) s += (double)lp[w];
        g_lp[c * NBLOCKS + blockIdx.x] = s;
    }
}

__global__ void rvq_loss_kernel(float* __restrict__ out, int lossOff)
{
    if (lossOff < 0) return;
    __shared__ double sd[256];
    int tid = threadIdx.x;
    double s = 0.0;
    for (int i = tid; i < NCB * NBLOCKS; i += 256) s += g_lp[i];
    sd[tid] = s;
    __syncthreads();
    for (int o = 128; o; o >>= 1) {
        if (tid < o) sd[tid] += sd[tid + o];
        __syncthreads();
    }
    if (tid == 0) out[lossOff] = (float)(sd[0] / (double)((long long)NROWS * DDIM));
}

extern "C" void kernel_launch(void* const* d_in, const int* in_sizes, int n_in,
                              void* d_out, int out_size)
{
    const float* z  = (const float*)d_in[0];
    const float* cb = (const float*)d_in[1];
    float* out = (float*)d_out;

    static bool attr_set = false;
    if (!attr_set) {
        cudaFuncSetAttribute(rvq_stage_kernel,
                             cudaFuncAttributeMaxDynamicSharedMemorySize, SMEMB);
        attr_set = true;
    }

    const int NZ = NROWS * DDIM, NIDX = NROWS * NCB;
    float* idxOut = nullptr;
    int lossOff = -1;
    if (out_size >= NZ + NIDX + 1) { idxOut = out + NZ; lossOff = NZ + NIDX; }
    else if (out_size == NZ + NIDX) { idxOut = out + NZ; }
    else if (out_size == NZ + 1)    { lossOff = NZ; }

    rvq_splitA_kernel<<<NROWS * 64 / 256, 256>>>(z);
    rvq_splitB_kernel<<<NCB * KCB * 64 / 256, 256>>>(cb);
    rvq_ww_kernel<<<NCB * KCB / 8, 256>>>(cb);

    for (int c = 0; c < NCB; c++)
        rvq_stage_kernel<<<NBLOCKS, TPB, SMEMB>>>(z, cb, out, idxOut, c);

    rvq_loss_kernel<<<1, 256>>>(out, lossOff);
}

// round 10
// speedup vs baseline: 1.5855x; 1.0136x over previous
#include <cuda_runtime.h>
#include <cuda_bf16.h>
#include <cstdint>

#define NROWS 65536
#define DDIM  256
#define NCB   8
#define KCB   1024
#define BM    128
#define TPB   512
#define NBLOCKS (NROWS / BM)     // 512
#define NKTI  16                 // 8 nb x 2 k-halves per stage

// -------- device scratch --------
__device__ float         g_res[(size_t)NROWS * DDIM];        // 64 MB fp32 residual
__device__ __nv_bfloat16 g_B1[(size_t)NCB * KCB * 256];      // bf16 codebooks
__device__ float         g_ww[NCB * KCB];
__device__ double        g_lp[NBLOCKS];

// -------- smem layout (bytes) --------
#define SO_SIDX 0          // 128 int
#define SO_RR   512        // 128 f
#define SO_LP   1024       // 16 f
#define SO_WW   4096       // 1024 f
#define SO_A    8192       // 64KB resident A: 128 rows x 256 bf16 (512B/row, swizzled)
#define SO_B    73728      // 2 x 32KB B ring
#define SO_CV   139264     // 128 x 64 float
#define SO_CI   172032     // 128 x 64 int
#define SMEMB   204800

__device__ __forceinline__ uint32_t smem_u32(const void* p) {
    uint32_t a;
    asm("{ .reg .u64 t; cvta.to.shared.u64 t, %1; cvt.u32.u64 %0, t; }" : "=r"(a) : "l"(p));
    return a;
}
__device__ __forceinline__ void cp16(uint32_t dst, const void* src) {
    asm volatile("cp.async.cg.shared.global [%0], [%1], 16;" :: "r"(dst), "l"(src));
}
#define CP_COMMIT() asm volatile("cp.async.commit_group;" ::: "memory")
#define CP_WAIT(n)  asm volatile("cp.async.wait_group %0;" :: "n"(n) : "memory")

__device__ __forceinline__ void ldsm4(uint32_t* r, uint32_t addr) {
    asm volatile("ldmatrix.sync.aligned.m8n8.x4.shared.b16 {%0,%1,%2,%3}, [%4];"
        : "=r"(r[0]), "=r"(r[1]), "=r"(r[2]), "=r"(r[3]) : "r"(addr));
}
__device__ __forceinline__ void mma16816(float* d, const uint32_t* a, uint32_t b0, uint32_t b1) {
    asm volatile(
        "mma.sync.aligned.m16n8k16.row.col.f32.bf16.bf16.f32 "
        "{%0,%1,%2,%3}, {%4,%5,%6,%7}, {%8,%9}, {%0,%1,%2,%3};"
        : "+f"(d[0]), "+f"(d[1]), "+f"(d[2]), "+f"(d[3])
        : "r"(a[0]), "r"(a[1]), "r"(a[2]), "r"(a[3]), "r"(b0), "r"(b1));
}
// sorted-ascending best-4 (lexicographic on (val, idx))
__device__ __forceinline__ void upd4(float* v, int* ix, float nv, int ni) {
    if (nv > v[3] || (nv == v[3] && ni > ix[3])) return;
    v[3] = nv; ix[3] = ni;
    #pragma unroll
    for (int p = 3; p > 0; p--) {
        bool sw = (v[p] < v[p-1]) || (v[p] == v[p-1] && ix[p] < ix[p-1]);
        if (sw) {
            float tv = v[p]; v[p] = v[p-1]; v[p-1] = tv;
            int   ti = ix[p]; ix[p] = ix[p-1]; ix[p-1] = ti;
        }
    }
}

// ---- prep kernels ----
__global__ void rvq_splitB_kernel(const float* __restrict__ cb)
{
    int id = blockIdx.x * 256 + threadIdx.x;
    int ck = id >> 6, d4 = id & 63;
    float4 v = *(const float4*)(cb + (size_t)ck * DDIM + d4 * 4);
    __nv_bfloat16 p1[4];
    p1[0] = __float2bfloat16_rn(v.x); p1[1] = __float2bfloat16_rn(v.y);
    p1[2] = __float2bfloat16_rn(v.z); p1[3] = __float2bfloat16_rn(v.w);
    *(uint64_t*)(g_B1 + (size_t)ck * 256 + d4 * 4) = *(uint64_t*)p1;
}
__global__ void rvq_ww_kernel(const float* __restrict__ cb)
{
    const int warp = threadIdx.x >> 5, lane = threadIdx.x & 31;
    const int k = blockIdx.x * 8 + warp;
    const float* w = cb + (size_t)k * DDIM;
    float s = 0.f;
    #pragma unroll
    for (int t = 0; t < 8; t++) { float v = w[lane + 32 * t]; s = fmaf(v, v, s); }
    #pragma unroll
    for (int o = 16; o; o >>= 1) s += __shfl_down_sync(0xffffffffu, s, o);
    if (lane == 0) g_ww[k] = s;
}

// ---- single fused kernel: all 8 stages ----
__global__ void __launch_bounds__(TPB)
rvq_fused_kernel(const float* __restrict__ z, const float* __restrict__ cb,
                 float* __restrict__ qOut, float* __restrict__ idxOut)
{
    extern __shared__ char smc[];
    const uint32_t sb = smem_u32(smc);
    int*   sIdx = (int*)(smc + SO_SIDX);
    float* rrsh = (float*)(smc + SO_RR);
    float* lp   = (float*)(smc + SO_LP);
    float* wws  = (float*)(smc + SO_WW);
    float* cv   = (float*)(smc + SO_CV);
    int*   ci   = (int*)(smc + SO_CI);

    const int tid  = threadIdx.x;
    const int lane = tid & 31;
    const int warp = tid >> 5;
    const int wr   = warp >> 2;      // 0..3 (32-row slice)
    const int wc   = warp & 3;       // 0..3 (32-col slice)
    const size_t rowbase = (size_t)blockIdx.x * BM;
    const int g = lane >> 2;

    const int arow0 = wr * 32 + (lane & 15);
    const int ukA = lane >> 4;
    const int ukB = (lane >> 3) & 1;
    const int brow_in = (lane & 7) + ((lane >> 4) << 3);
    const int erow = tid >> 2, eq = tid & 3;     // epilogue: 4 threads/row

    // ---- stage-0 init: fill resident A (bf16, swizzled) + rr from z ----
    {
        const float* rp = z + (rowbase + erow) * DDIM;
        float s = 0.f;
        #pragma unroll
        for (int t = 0; t < 16; t++) {
            int d4 = eq + 4 * t;
            float4 v = *(const float4*)(rp + d4 * 4);
            __nv_bfloat16 p1[4];
            p1[0] = __float2bfloat16_rn(v.x); p1[1] = __float2bfloat16_rn(v.y);
            p1[2] = __float2bfloat16_rn(v.z); p1[3] = __float2bfloat16_rn(v.w);
            int u = d4 >> 1;
            *(uint64_t*)(smc + SO_A + erow * 512 + ((u ^ (erow & 7)) << 4) + (d4 & 1) * 8)
                = *(uint64_t*)p1;
            s = fmaf(v.x, v.x, s); s = fmaf(v.y, v.y, s);
            s = fmaf(v.z, v.z, s); s = fmaf(v.w, v.w, s);
        }
        s += __shfl_xor_sync(0xffffffffu, s, 1);
        s += __shfl_xor_sync(0xffffffffu, s, 2);
        if (eq == 0) rrsh[erow] = s;
    }
    __syncthreads();

    // B prefetch: tile (cq, nb, half) -> ring buffer b
    auto pfB = [&](int cq, int nb_t, int half, int b) {
        const size_t base = ((size_t)(cq * KCB + nb_t * 128)) * 256 + half * 128;
        const uint32_t bbase = sb + SO_B + b * 32768;
        #pragma unroll
        for (int i = 0; i < 4; i++) {
            int v = tid + TPB * i;
            int nrow = v >> 4, u = v & 15;
            cp16(bbase + nrow * 256 + ((u ^ (nrow & 7)) << 4),
                 g_B1 + base + (size_t)nrow * 256 + u * 8);
        }
    };

    pfB(0, 0, 0, 0); CP_COMMIT();
    pfB(0, 0, 1, 1); CP_COMMIT();

    double lossAcc = 0.0;

    #pragma unroll 1
    for (int c = 0; c < NCB; c++) {
        const float* resIn = (c == 0) ? z : g_res;
        const float* cbc = cb + (size_t)c * KCB * DDIM;
        for (int i = tid; i < KCB; i += TPB) wws[i] = g_ww[c * KCB + i];

        float rrl[4];
        #pragma unroll
        for (int mf = 0; mf < 2; mf++)
            #pragma unroll
            for (int h = 0; h < 2; h++)
                rrl[mf * 2 + h] = rrsh[wr * 32 + mf * 16 + g + 8 * h];

        float cv4[16]; int ci4[16];
        #pragma unroll
        for (int i = 0; i < 16; i++) { cv4[i] = 3.0e38f; ci4[i] = 0x7fffffff; }

        float acc[2][4][4];

        #pragma unroll 1
        for (int kti = 0; kti < NKTI; kti++) {
            CP_WAIT(1);
            __syncthreads();
            const int nb = kti >> 1, ktHalf = kti & 1;
            if (ktHalf == 0) {
                #pragma unroll
                for (int mf = 0; mf < 2; mf++)
                    #pragma unroll
                    for (int j = 0; j < 4; j++)
                        #pragma unroll
                        for (int e = 0; e < 4; e++) acc[mf][j][e] = 0.f;
            }
            const uint32_t abase = sb + SO_A;
            const uint32_t bbase = sb + SO_B + (kti & 1) * 32768;
            #pragma unroll
            for (int s = 0; s < 8; s++) {
                uint32_t a[2][4];
                #pragma unroll
                for (int mf = 0; mf < 2; mf++) {
                    int r = arow0 + mf * 16;
                    int u = ktHalf * 16 + s * 2 + ukA;
                    ldsm4(a[mf], abase + r * 512 + ((u ^ (r & 7)) << 4));
                }
                uint32_t b[4][2];
                #pragma unroll
                for (int nf4 = 0; nf4 < 2; nf4++) {
                    int r = wc * 32 + nf4 * 16 + brow_in;
                    int u = s * 2 + ukB;
                    uint32_t t[4];
                    ldsm4(t, bbase + r * 256 + ((u ^ (r & 7)) << 4));
                    b[nf4 * 2][0] = t[0]; b[nf4 * 2][1] = t[1];
                    b[nf4 * 2 + 1][0] = t[2]; b[nf4 * 2 + 1][1] = t[3];
                }
                #pragma unroll
                for (int mf = 0; mf < 2; mf++)
                    #pragma unroll
                    for (int j = 0; j < 4; j++)
                        mma16816(acc[mf][j], a[mf], b[j][0], b[j][1]);
            }
            __syncthreads();   // ring safety: all reads of this buffer done
            {
                int tgt = kti + 2;
                if (tgt < NKTI) pfB(c, tgt >> 1, tgt & 1, kti & 1);
                else {
                    int cn = (c + 1 < NCB) ? c + 1 : NCB - 1;   // clamp (stage 7: harmless reload)
                    pfB(cn, 0, tgt - NKTI, kti & 1);
                }
                CP_COMMIT();
            }
            if (ktHalf == 1) {
                #pragma unroll
                for (int mf = 0; mf < 2; mf++) {
                    #pragma unroll
                    for (int h = 0; h < 2; h++) {
                        const int ridx = mf * 2 + h;
                        const float rrv = rrl[ridx];
                        #pragma unroll
                        for (int j = 0; j < 4; j++) {
                            #pragma unroll
                            for (int e = 0; e < 2; e++) {
                                int col = nb * 128 + wc * 32 + j * 8 + (lane & 3) * 2 + e;
                                float d2 = fmaf(-2.0f, acc[mf][j][h * 2 + e], rrv) + wws[col];
                                upd4(cv4 + ridx * 4, ci4 + ridx * 4, d2, col);
                            }
                        }
                    }
                }
            }
        }

        // dump best-4 lists: 128 rows x 64 slots
        #pragma unroll
        for (int mf = 0; mf < 2; mf++)
            #pragma unroll
            for (int h = 0; h < 2; h++) {
                int row = wr * 32 + mf * 16 + g + 8 * h;
                int slot = wc * 16 + (lane & 3) * 4;
                #pragma unroll
                for (int s = 0; s < 4; s++) {
                    cv[row * 64 + slot + s] = cv4[(mf * 2 + h) * 4 + s];
                    ci[row * 64 + slot + s] = ci4[(mf * 2 + h) * 4 + s];
                }
            }
        __syncthreads();

        // exact rescore (reproduces the reference d2 pipeline bit-for-bit)
        if (tid < BM) {
            const float* cvr = cv + tid * 64;
            const int*   cir = ci + tid * 64;
            float mv = cvr[0];
            #pragma unroll
            for (int s = 1; s < 64; s++) mv = fminf(mv, cvr[s]);
            const float band = 3e-3f;

            const float* rp = resIn + (rowbase + tid) * DDIM;
            float q[4];
            #pragma unroll
            for (int qq = 0; qq < 4; qq++) {
                float s = 0.f;
                #pragma unroll
                for (int i = 0; i < 16; i++) {
                    float4 v = *(const float4*)(rp + qq * 64 + i * 4);
                    s = fmaf(v.x, v.x, s); s = fmaf(v.y, v.y, s);
                    s = fmaf(v.z, v.z, s); s = fmaf(v.w, v.w, s);
                }
                q[qq] = s;
            }
            float rr = ((q[0] + q[1]) + q[2]) + q[3];

            float bv = 3.0e38f; int bi = 0x7fffffff;
            for (int s = 0; s < 64; s++) {
                if (cvr[s] <= mv + band) {
                    int k = cir[s];
                    const float* w = cbc + (size_t)k * DDIM;
                    float acc2 = 0.f;
                    #pragma unroll 8
                    for (int i = 0; i < 64; i++) {
                        float4 rv = *(const float4*)(rp + i * 4);
                        float4 wv = *(const float4*)(w + i * 4);
                        acc2 = fmaf(rv.x, wv.x, acc2); acc2 = fmaf(rv.y, wv.y, acc2);
                        acc2 = fmaf(rv.z, wv.z, acc2); acc2 = fmaf(rv.w, wv.w, acc2);
                    }
                    float t  = fmaf(-2.0f, acc2, rr);
                    float d2 = t + wws[k];
                    if (d2 < bv || (d2 == bv && k < bi)) { bv = d2; bi = k; }
                }
            }
            sIdx[tid] = bi;
            if (idxOut) idxOut[(rowbase + tid) * NCB + c] = (float)bi;
        }
        __syncthreads();

        // epilogue: residual/quantized update + loss + next-stage A (smem) + rr
        {
            size_t grow = rowbase + erow;
            const float* wrow = cbc + (size_t)sIdx[erow] * DDIM;
            const float* rrow = resIn + grow * DDIM;
            float* ro = g_res + grow * DDIM;
            float* qo = qOut + grow * DDIM;
            float lsum = 0.f;
            #pragma unroll
            for (int t = 0; t < 16; t++) {
                int d4 = eq + 4 * t;
                float4 w4 = *(const float4*)(wrow + d4 * 4);
                float4 r4 = *(const float4*)(rrow + d4 * 4);
                float4 nr;
                nr.x = r4.x - w4.x; nr.y = r4.y - w4.y;
                nr.z = r4.z - w4.z; nr.w = r4.w - w4.w;
                *(float4*)(ro + d4 * 4) = nr;
                float4 qv;
                if (c == 0) qv = w4;
                else {
                    float4 qp = *(const float4*)(qo + d4 * 4);
                    qv.x = qp.x + w4.x; qv.y = qp.y + w4.y;
                    qv.z = qp.z + w4.z; qv.w = qp.w + w4.w;
                }
                *(float4*)(qo + d4 * 4) = qv;
                lsum = fmaf(nr.x, nr.x, lsum); lsum = fmaf(nr.y, nr.y, lsum);
                lsum = fmaf(nr.z, nr.z, lsum); lsum = fmaf(nr.w, nr.w, lsum);
                if (c < 7) {
                    __nv_bfloat16 p1[4];
                    p1[0] = __float2bfloat16_rn(nr.x); p1[1] = __float2bfloat16_rn(nr.y);
                    p1[2] = __float2bfloat16_rn(nr.z); p1[3] = __float2bfloat16_rn(nr.w);
                    int u = d4 >> 1;
                    *(uint64_t*)(smc + SO_A + erow * 512 + ((u ^ (erow & 7)) << 4) + (d4 & 1) * 8)
                        = *(uint64_t*)p1;
                }
            }
            // quad sum -> next-stage rr (filter only)
            float qsum = lsum;
            qsum += __shfl_xor_sync(0xffffffffu, qsum, 1);
            qsum += __shfl_xor_sync(0xffffffffu, qsum, 2);
            if (eq == 0) rrsh[erow] = qsum;
            // full warp sum -> loss partial
            float wsum = lsum;
            #pragma unroll
            for (int o = 16; o; o >>= 1) wsum += __shfl_xor_sync(0xffffffffu, wsum, o);
            if (lane == 0) lp[warp] = wsum;
        }
        __syncthreads();
        if (tid == 0) {
            double s = 0.0;
            #pragma unroll
            for (int w = 0; w < 16; w++) s += (double)lp[w];
            lossAcc += s;
        }
        __syncthreads();
    }
    if (tid == 0) g_lp[blockIdx.x] = lossAcc;
}

__global__ void rvq_loss_kernel(float* __restrict__ out, int lossOff)
{
    if (lossOff < 0) return;
    __shared__ double sd[256];
    int tid = threadIdx.x;
    double s = 0.0;
    for (int i = tid; i < NBLOCKS; i += 256) s += g_lp[i];
    sd[tid] = s;
    __syncthreads();
    for (int o = 128; o; o >>= 1) {
        if (tid < o) sd[tid] += sd[tid + o];
        __syncthreads();
    }
    if (tid == 0) out[lossOff] = (float)(sd[0] / (double)((long long)NROWS * DDIM));
}

extern "C" void kernel_launch(void* const* d_in, const int* in_sizes, int n_in,
                              void* d_out, int out_size)
{
    const float* z  = (const float*)d_in[0];
    const float* cb = (const float*)d_in[1];
    float* out = (float*)d_out;

    static bool attr_set = false;
    if (!attr_set) {
        cudaFuncSetAttribute(rvq_fused_kernel,
                             cudaFuncAttributeMaxDynamicSharedMemorySize, SMEMB);
        attr_set = true;
    }

    const int NZ = NROWS * DDIM, NIDX = NROWS * NCB;
    float* idxOut = nullptr;
    int lossOff = -1;
    if (out_size >= NZ + NIDX + 1) { idxOut = out + NZ; lossOff = NZ + NIDX; }
    else if (out_size == NZ + NIDX) { idxOut = out + NZ; }
    else if (out_size == NZ + 1)    { lossOff = NZ; }

    rvq_splitB_kernel<<<NCB * KCB * 64 / 256, 256>>>(cb);
    rvq_ww_kernel<<<NCB * KCB / 8, 256>>>(cb);
    rvq_fused_kernel<<<NBLOCKS, TPB, SMEMB>>>(z, cb, out, idxOut);
    rvq_loss_kernel<<<1, 256>>>(out, lossOff);
}

// round 16
// speedup vs baseline: 1.9007x; 1.1988x over previous
// rvq_fused v15 (R14 resubmission, cache-bust tag: r15a)
#include <cuda_runtime.h>
#include <cuda_bf16.h>
#include <cstdint>

#define NROWS 65536
#define DDIM  256
#define NCB   8
#define KCB   1024
#define BM    64
#define TPB   256
#define NBLOCKS (NROWS / BM)     // 1024
#define NKTI  32                 // 8 nb x 4 k-quarters per stage

// -------- device scratch --------
__device__ float         g_res[(size_t)NROWS * DDIM];        // 64 MB fp32 residual
__device__ __nv_bfloat16 g_B1[(size_t)NCB * KCB * 256];      // bf16 codebooks
__device__ float         g_ww[NCB * KCB];
__device__ double        g_lp[NBLOCKS];

// -------- smem layout (bytes) --------
#define SO_SIDX 0          // 64 int
#define SO_RR   256        // 64 f
#define SO_LP   512        // 8 f
#define SO_WW   1024       // 1024 f (4KB)
#define SO_A    5120       // 32KB resident A: 64 rows x 256 bf16 (512B/row, swizzled)
#define SO_B    37888      // 2 x 16KB B ring (128 codewords x 64 dims)
#define SO_CV   70656      // 64 x 64 float
#define SO_CI   87040      // 64 x 64 int
#define SMEMB   103424     // x2 = 206848 <= 228KB/SM -> 2 CTAs/SM

__device__ __forceinline__ uint32_t smem_u32(const void* p) {
    uint32_t a;
    asm("{ .reg .u64 t; cvta.to.shared.u64 t, %1; cvt.u32.u64 %0, t; }" : "=r"(a) : "l"(p));
    return a;
}
__device__ __forceinline__ void cp16(uint32_t dst, const void* src) {
    asm volatile("cp.async.cg.shared.global [%0], [%1], 16;" :: "r"(dst), "l"(src));
}
#define CP_COMMIT() asm volatile("cp.async.commit_group;" ::: "memory")
#define CP_WAIT(n)  asm volatile("cp.async.wait_group %0;" :: "n"(n) : "memory")

__device__ __forceinline__ void ldsm4(uint32_t* r, uint32_t addr) {
    asm volatile("ldmatrix.sync.aligned.m8n8.x4.shared.b16 {%0,%1,%2,%3}, [%4];"
        : "=r"(r[0]), "=r"(r[1]), "=r"(r[2]), "=r"(r[3]) : "r"(addr));
}
__device__ __forceinline__ void mma16816(float* d, const uint32_t* a, uint32_t b0, uint32_t b1) {
    asm volatile(
        "mma.sync.aligned.m16n8k16.row.col.f32.bf16.bf16.f32 "
        "{%0,%1,%2,%3}, {%4,%5,%6,%7}, {%8,%9}, {%0,%1,%2,%3};"
        : "+f"(d[0]), "+f"(d[1]), "+f"(d[2]), "+f"(d[3])
        : "r"(a[0]), "r"(a[1]), "r"(a[2]), "r"(a[3]), "r"(b0), "r"(b1));
}
// sorted-ascending best-4 (lexicographic on (val, idx))
__device__ __forceinline__ void upd4(float* v, int* ix, float nv, int ni) {
    if (nv > v[3] || (nv == v[3] && ni > ix[3])) return;
    v[3] = nv; ix[3] = ni;
    #pragma unroll
    for (int p = 3; p > 0; p--) {
        bool sw = (v[p] < v[p-1]) || (v[p] == v[p-1] && ix[p] < ix[p-1]);
        if (sw) {
            float tv = v[p]; v[p] = v[p-1]; v[p-1] = tv;
            int   ti = ix[p]; ix[p] = ix[p-1]; ix[p-1] = ti;
        }
    }
}

// ---- prep kernels ----
__global__ void rvq_splitB_kernel(const float* __restrict__ cb)
{
    int id = blockIdx.x * 256 + threadIdx.x;
    int ck = id >> 6, d4 = id & 63;
    float4 v = *(const float4*)(cb + (size_t)ck * DDIM + d4 * 4);
    __nv_bfloat16 p1[4];
    p1[0] = __float2bfloat16_rn(v.x); p1[1] = __float2bfloat16_rn(v.y);
    p1[2] = __float2bfloat16_rn(v.z); p1[3] = __float2bfloat16_rn(v.w);
    *(uint64_t*)(g_B1 + (size_t)ck * 256 + d4 * 4) = *(uint64_t*)p1;
}
__global__ void rvq_ww_kernel(const float* __restrict__ cb)
{
    const int warp = threadIdx.x >> 5, lane = threadIdx.x & 31;
    const int k = blockIdx.x * 8 + warp;
    const float* w = cb + (size_t)k * DDIM;
    float s = 0.f;
    #pragma unroll
    for (int t = 0; t < 8; t++) { float v = w[lane + 32 * t]; s = fmaf(v, v, s); }
    #pragma unroll
    for (int o = 16; o; o >>= 1) s += __shfl_down_sync(0xffffffffu, s, o);
    if (lane == 0) g_ww[k] = s;
}

// ---- single fused kernel: all 8 stages, 2 CTAs/SM ----
__global__ void __launch_bounds__(TPB, 2)
rvq_fused_kernel(const float* __restrict__ z, const float* __restrict__ cb,
                 float* __restrict__ qOut, float* __restrict__ idxOut)
{
    extern __shared__ char smc[];
    const uint32_t sb = smem_u32(smc);
    int*   sIdx = (int*)(smc + SO_SIDX);
    float* rrsh = (float*)(smc + SO_RR);
    float* lp   = (float*)(smc + SO_LP);
    float* wws  = (float*)(smc + SO_WW);
    float* cv   = (float*)(smc + SO_CV);
    int*   ci   = (int*)(smc + SO_CI);

    const int tid  = threadIdx.x;
    const int lane = tid & 31;
    const int warp = tid >> 5;
    const int wr   = warp >> 2;      // 0..1 (32-row slice)
    const int wc   = warp & 3;       // 0..3 (32-col slice)
    const size_t rowbase = (size_t)blockIdx.x * BM;
    const int g = lane >> 2;

    const int arow0 = wr * 32 + (lane & 15);
    const int ukA = lane >> 4;
    const int ukB = (lane >> 3) & 1;
    const int brow_in = (lane & 7) + ((lane >> 4) << 3);
    const int erow = tid >> 2, eq = tid & 3;     // 4 threads/row phases
    const uint32_t qmask = 0xFu << (lane & ~3);  // quad-scoped shfl mask
    const int qbase = lane & ~3;

    // ---- stage-0 init: fill resident A (bf16, swizzled) + rr from z ----
    {
        const float* rp = z + (rowbase + erow) * DDIM;
        float s = 0.f;
        #pragma unroll
        for (int t = 0; t < 16; t++) {
            int d4 = eq + 4 * t;
            float4 v = *(const float4*)(rp + d4 * 4);
            __nv_bfloat16 p1[4];
            p1[0] = __float2bfloat16_rn(v.x); p1[1] = __float2bfloat16_rn(v.y);
            p1[2] = __float2bfloat16_rn(v.z); p1[3] = __float2bfloat16_rn(v.w);
            int u = d4 >> 1;
            *(uint64_t*)(smc + SO_A + erow * 512 + ((u ^ (erow & 7)) << 4) + (d4 & 1) * 8)
                = *(uint64_t*)p1;
            s = fmaf(v.x, v.x, s); s = fmaf(v.y, v.y, s);
            s = fmaf(v.z, v.z, s); s = fmaf(v.w, v.w, s);
        }
        s += __shfl_xor_sync(0xffffffffu, s, 1);
        s += __shfl_xor_sync(0xffffffffu, s, 2);
        if (eq == 0) rrsh[erow] = s;
    }
    __syncthreads();

    // B prefetch: tile (cq, nb, quarter) -> ring buffer b (128 cw x 64 dims = 16KB)
    auto pfB = [&](int cq, int nb_t, int q, int b) {
        const size_t base = ((size_t)(cq * KCB + nb_t * 128)) * 256 + q * 64;
        const uint32_t bbase = sb + SO_B + b * 16384;
        #pragma unroll
        for (int i = 0; i < 4; i++) {
            int v = tid + TPB * i;           // 1024 16B units
            int nrow = v >> 3, u = v & 7;
            cp16(bbase + nrow * 128 + ((u ^ (nrow & 7)) << 4),
                 g_B1 + base + (size_t)nrow * 256 + u * 8);
        }
    };

    pfB(0, 0, 0, 0); CP_COMMIT();
    pfB(0, 0, 1, 1); CP_COMMIT();

    double lossAcc = 0.0;

    #pragma unroll 1
    for (int c = 0; c < NCB; c++) {
        const float* resIn = (c == 0) ? z : g_res;
        const float* cbc = cb + (size_t)c * KCB * DDIM;
        for (int i = tid; i < KCB; i += TPB) wws[i] = g_ww[c * KCB + i];

        float rrl[4];
        #pragma unroll
        for (int mf = 0; mf < 2; mf++)
            #pragma unroll
            for (int h = 0; h < 2; h++)
                rrl[mf * 2 + h] = rrsh[wr * 32 + mf * 16 + g + 8 * h];

        float cv4[16]; int ci4[16];
        #pragma unroll
        for (int i = 0; i < 16; i++) { cv4[i] = 3.0e38f; ci4[i] = 0x7fffffff; }

        float acc[2][4][4];

        #pragma unroll 1
        for (int kti = 0; kti < NKTI; kti++) {
            CP_WAIT(1);
            __syncthreads();
            const int nb = kti >> 2, kq = kti & 3;
            if (kq == 0) {
                #pragma unroll
                for (int mf = 0; mf < 2; mf++)
                    #pragma unroll
                    for (int j = 0; j < 4; j++)
                        #pragma unroll
                        for (int e = 0; e < 4; e++) acc[mf][j][e] = 0.f;
            }
            const uint32_t abase = sb + SO_A;
            const uint32_t bbase = sb + SO_B + (kti & 1) * 16384;
            #pragma unroll
            for (int s = 0; s < 4; s++) {
                uint32_t a[2][4];
                #pragma unroll
                for (int mf = 0; mf < 2; mf++) {
                    int r = arow0 + mf * 16;
                    int u = kq * 8 + s * 2 + ukA;
                    ldsm4(a[mf], abase + r * 512 + ((u ^ (r & 7)) << 4));
                }
                uint32_t b[4][2];
                #pragma unroll
                for (int nf4 = 0; nf4 < 2; nf4++) {
                    int r = wc * 32 + nf4 * 16 + brow_in;
                    int u = s * 2 + ukB;
                    uint32_t t[4];
                    ldsm4(t, bbase + r * 128 + ((u ^ (r & 7)) << 4));
                    b[nf4 * 2][0] = t[0]; b[nf4 * 2][1] = t[1];
                    b[nf4 * 2 + 1][0] = t[2]; b[nf4 * 2 + 1][1] = t[3];
                }
                #pragma unroll
                for (int mf = 0; mf < 2; mf++)
                    #pragma unroll
                    for (int j = 0; j < 4; j++)
                        mma16816(acc[mf][j], a[mf], b[j][0], b[j][1]);
            }
            __syncthreads();   // ring safety: all reads of this buffer done
            {
                int tgt = kti + 2;
                if (tgt < NKTI) pfB(c, tgt >> 2, tgt & 3, kti & 1);
                else {
                    int cn = (c + 1 < NCB) ? c + 1 : NCB - 1;   // clamp (stage 7: harmless)
                    pfB(cn, 0, tgt - NKTI, kti & 1);
                }
                CP_COMMIT();
            }
            if (kq == 3) {
                #pragma unroll
                for (int mf = 0; mf < 2; mf++) {
                    #pragma unroll
                    for (int h = 0; h < 2; h++) {
                        const int ridx = mf * 2 + h;
                        const float rrv = rrl[ridx];
                        #pragma unroll
                        for (int j = 0; j < 4; j++) {
                            #pragma unroll
                            for (int e = 0; e < 2; e++) {
                                int col = nb * 128 + wc * 32 + j * 8 + (lane & 3) * 2 + e;
                                float d2 = fmaf(-2.0f, acc[mf][j][h * 2 + e], rrv) + wws[col];
                                upd4(cv4 + ridx * 4, ci4 + ridx * 4, d2, col);
                            }
                        }
                    }
                }
            }
        }

        // dump best-4 lists: 64 rows x 64 slots
        #pragma unroll
        for (int mf = 0; mf < 2; mf++)
            #pragma unroll
            for (int h = 0; h < 2; h++) {
                int row = wr * 32 + mf * 16 + g + 8 * h;
                int slot = wc * 16 + (lane & 3) * 4;
                #pragma unroll
                for (int s = 0; s < 4; s++) {
                    cv[row * 64 + slot + s] = cv4[(mf * 2 + h) * 4 + s];
                    ci[row * 64 + slot + s] = ci4[(mf * 2 + h) * 4 + s];
                }
            }
        __syncthreads();

        // exact rescore: candidates parallelized ACROSS the quad; each thread
        // runs the FULL sequential 256-FMA dot chain (bit-identical to the
        // reference-proven R10 pipeline). rr quarters computed per-thread with
        // the identical ascending chains, shfl-broadcast, combined in the
        // identical ((q0+q1)+q2)+q3 order. Final quad argmin is a lexicographic
        // set-min => order-independent => bitwise-identical winner.
        {
            const float* cvr = cv + erow * 64;
            const int*   cir = ci + erow * 64;
            float mv = cvr[0];
            #pragma unroll
            for (int s = 1; s < 64; s++) mv = fminf(mv, cvr[s]);
            const float band = 3e-3f;

            const float* rp = resIn + (rowbase + erow) * DDIM;
            // quarter rr (thread eq owns quarter eq; chain identical to R10)
            float qv = 0.f;
            #pragma unroll
            for (int i = 0; i < 16; i++) {
                float4 v = *(const float4*)(rp + eq * 64 + i * 4);
                qv = fmaf(v.x, v.x, qv); qv = fmaf(v.y, v.y, qv);
                qv = fmaf(v.z, v.z, qv); qv = fmaf(v.w, v.w, qv);
            }
            float q0 = __shfl_sync(qmask, qv, qbase + 0);
            float q1 = __shfl_sync(qmask, qv, qbase + 1);
            float q2 = __shfl_sync(qmask, qv, qbase + 2);
            float q3 = __shfl_sync(qmask, qv, qbase + 3);
            float rr = ((q0 + q1) + q2) + q3;

            float bv = 3.0e38f; int bi = 0x7fffffff;
            #pragma unroll 1
            for (int s = eq; s < 64; s += 4) {       // uniform trip count (16)
                if (cvr[s] <= mv + band) {           // divergent, but no collectives inside
                    int k = cir[s];
                    const float* w = cbc + (size_t)k * DDIM;
                    float acc2 = 0.f;
                    #pragma unroll 8
                    for (int i = 0; i < 64; i++) {   // full sequential 256-FMA chain (R10-exact)
                        float4 rv = *(const float4*)(rp + i * 4);
                        float4 wv = *(const float4*)(w + i * 4);
                        acc2 = fmaf(rv.x, wv.x, acc2); acc2 = fmaf(rv.y, wv.y, acc2);
                        acc2 = fmaf(rv.z, wv.z, acc2); acc2 = fmaf(rv.w, wv.w, acc2);
                    }
                    float t  = fmaf(-2.0f, acc2, rr);
                    float d2 = t + wws[k];
                    if (d2 < bv || (d2 == bv && k < bi)) { bv = d2; bi = k; }
                }
            }
            // quad argmin reduce (uniform control flow; exact comparisons)
            #pragma unroll
            for (int o = 1; o <= 2; o <<= 1) {
                float ov = __shfl_xor_sync(qmask, bv, o);
                int   oi = __shfl_xor_sync(qmask, bi, o);
                if (ov < bv || (ov == bv && oi < bi)) { bv = ov; bi = oi; }
            }
            if (eq == 0) {
                sIdx[erow] = bi;
                if (idxOut) idxOut[(rowbase + erow) * NCB + c] = (float)bi;
            }
        }
        __syncthreads();

        // epilogue: residual/quantized update + loss + next-stage A (smem) + rr
        {
            size_t grow = rowbase + erow;
            const float* wrow = cbc + (size_t)sIdx[erow] * DDIM;
            const float* rrow = resIn + grow * DDIM;
            float* ro = g_res + grow * DDIM;
            float* qo = qOut + grow * DDIM;
            float lsum = 0.f;
            #pragma unroll
            for (int t = 0; t < 16; t++) {
                int d4 = eq + 4 * t;
                float4 w4 = *(const float4*)(wrow + d4 * 4);
                float4 r4 = *(const float4*)(rrow + d4 * 4);
                float4 nr;
                nr.x = r4.x - w4.x; nr.y = r4.y - w4.y;
                nr.z = r4.z - w4.z; nr.w = r4.w - w4.w;
                *(float4*)(ro + d4 * 4) = nr;
                float4 qv2;
                if (c == 0) qv2 = w4;
                else {
                    float4 qp = *(const float4*)(qo + d4 * 4);
                    qv2.x = qp.x + w4.x; qv2.y = qp.y + w4.y;
                    qv2.z = qp.z + w4.z; qv2.w = qp.w + w4.w;
                }
                *(float4*)(qo + d4 * 4) = qv2;
                lsum = fmaf(nr.x, nr.x, lsum); lsum = fmaf(nr.y, nr.y, lsum);
                lsum = fmaf(nr.z, nr.z, lsum); lsum = fmaf(nr.w, nr.w, lsum);
                if (c < 7) {
                    __nv_bfloat16 p1[4];
                    p1[0] = __float2bfloat16_rn(nr.x); p1[1] = __float2bfloat16_rn(nr.y);
                    p1[2] = __float2bfloat16_rn(nr.z); p1[3] = __float2bfloat16_rn(nr.w);
                    int u = d4 >> 1;
                    *(uint64_t*)(smc + SO_A + erow * 512 + ((u ^ (erow & 7)) << 4) + (d4 & 1) * 8)
                        = *(uint64_t*)p1;
                }
            }
            // quad sum -> next-stage rr (filter only)
            float qsum = lsum;
            qsum += __shfl_xor_sync(0xffffffffu, qsum, 1);
            qsum += __shfl_xor_sync(0xffffffffu, qsum, 2);
            if (eq == 0) rrsh[erow] = qsum;
            // full warp sum -> loss partial
            float wsum = lsum;
            #pragma unroll
            for (int o = 16; o; o >>= 1) wsum += __shfl_xor_sync(0xffffffffu, wsum, o);
            if (lane == 0) lp[warp] = wsum;
        }
        __syncthreads();
        if (tid == 0) {
            double s = 0.0;
            #pragma unroll
            for (int w = 0; w < 8; w++) s += (double)lp[w];
            lossAcc += s;
        }
        __syncthreads();
    }
    if (tid == 0) g_lp[blockIdx.x] = lossAcc;
}

__global__ void rvq_loss_kernel(float* __restrict__ out, int lossOff)
{
    if (lossOff < 0) return;
    __shared__ double sd[256];
    int tid = threadIdx.x;
    double s = 0.0;
    for (int i = tid; i < NBLOCKS; i += 256) s += g_lp[i];
    sd[tid] = s;
    __syncthreads();
    for (int o = 128; o; o >>= 1) {
        if (tid < o) sd[tid] += sd[tid + o];
        __syncthreads();
    }
    if (tid == 0) out[lossOff] = (float)(sd[0] / (double)((long long)NROWS * DDIM));
}

extern "C" void kernel_launch(void* const* d_in, const int* in_sizes, int n_in,
                              void* d_out, int out_size)
{
    const float* z  = (const float*)d_in[0];
    const float* cb = (const float*)d_in[1];
    float* out = (float*)d_out;

    static bool attr_set = false;
    if (!attr_set) {
        cudaFuncSetAttribute(rvq_fused_kernel,
                             cudaFuncAttributeMaxDynamicSharedMemorySize, SMEMB);
        attr_set = true;
    }

    const int NZ = NROWS * DDIM, NIDX = NROWS * NCB;
    float* idxOut = nullptr;
    int lossOff = -1;
    if (out_size >= NZ + NIDX + 1) { idxOut = out + NZ; lossOff = NZ + NIDX; }
    else if (out_size == NZ + NIDX) { idxOut = out + NZ; }
    else if (out_size == NZ + 1)    { lossOff = NZ; }

    rvq_splitB_kernel<<<NCB * KCB * 64 / 256, 256>>>(cb);
    rvq_ww_kernel<<<NCB * KCB / 8, 256>>>(cb);
    rvq_fused_kernel<<<NBLOCKS, TPB, SMEMB>>>(z, cb, out, idxOut);
    rvq_loss_kernel<<<1, 256>>>(out, lossOff);
}

// round 17
// speedup vs baseline: 1.9057x; 1.0026x over previous
// rvq_fused v17: 3-deep B ring, single barrier per k-iter, cv/ci overlay
#include <cuda_runtime.h>
#include <cuda_bf16.h>
#include <cstdint>

#define NROWS 65536
#define DDIM  256
#define NCB   8
#define KCB   1024
#define BM    64
#define TPB   256
#define NBLOCKS (NROWS / BM)     // 1024
#define NKTI  32                 // 8 nb x 4 k-quarters per stage

// -------- device scratch --------
__device__ float         g_res[(size_t)NROWS * DDIM];        // 64 MB fp32 residual
__device__ __nv_bfloat16 g_B1[(size_t)NCB * KCB * 256];      // bf16 codebooks
__device__ float         g_ww[NCB * KCB];
__device__ double        g_lp[NBLOCKS];

// -------- smem layout (bytes) --------
#define SO_SIDX 0          // 64 int
#define SO_RR   256        // 64 f
#define SO_LP   512        // 8 f
#define SO_WW   1024       // 1024 f (4KB)
#define SO_A    5120       // 32KB resident A: 64 rows x 256 bf16 (512B/row, swizzled)
#define SO_B    37888      // 3 x 16KB B ring (128 codewords x 64 dims each)
#define SO_CV   37888      // overlay on B buf0 (dead after GEMM): 64x64 float
#define SO_CI   54272      // overlay on B buf1: 64x64 int
#define SMEMB   87040      // x2 = 174080 <= 228KB/SM -> 2 CTAs/SM

__device__ __forceinline__ uint32_t smem_u32(const void* p) {
    uint32_t a;
    asm("{ .reg .u64 t; cvta.to.shared.u64 t, %1; cvt.u32.u64 %0, t; }" : "=r"(a) : "l"(p));
    return a;
}
__device__ __forceinline__ void cp16(uint32_t dst, const void* src) {
    asm volatile("cp.async.cg.shared.global [%0], [%1], 16;" :: "r"(dst), "l"(src));
}
#define CP_COMMIT() asm volatile("cp.async.commit_group;" ::: "memory")
#define CP_WAIT(n)  asm volatile("cp.async.wait_group %0;" :: "n"(n) : "memory")

__device__ __forceinline__ void ldsm4(uint32_t* r, uint32_t addr) {
    asm volatile("ldmatrix.sync.aligned.m8n8.x4.shared.b16 {%0,%1,%2,%3}, [%4];"
        : "=r"(r[0]), "=r"(r[1]), "=r"(r[2]), "=r"(r[3]) : "r"(addr));
}
__device__ __forceinline__ void mma16816(float* d, const uint32_t* a, uint32_t b0, uint32_t b1) {
    asm volatile(
        "mma.sync.aligned.m16n8k16.row.col.f32.bf16.bf16.f32 "
        "{%0,%1,%2,%3}, {%4,%5,%6,%7}, {%8,%9}, {%0,%1,%2,%3};"
        : "+f"(d[0]), "+f"(d[1]), "+f"(d[2]), "+f"(d[3])
        : "r"(a[0]), "r"(a[1]), "r"(a[2]), "r"(a[3]), "r"(b0), "r"(b1));
}
// sorted-ascending best-4 (lexicographic on (val, idx))
__device__ __forceinline__ void upd4(float* v, int* ix, float nv, int ni) {
    if (nv > v[3] || (nv == v[3] && ni > ix[3])) return;
    v[3] = nv; ix[3] = ni;
    #pragma unroll
    for (int p = 3; p > 0; p--) {
        bool sw = (v[p] < v[p-1]) || (v[p] == v[p-1] && ix[p] < ix[p-1]);
        if (sw) {
            float tv = v[p]; v[p] = v[p-1]; v[p-1] = tv;
            int   ti = ix[p]; ix[p] = ix[p-1]; ix[p-1] = ti;
        }
    }
}

// ---- prep kernels ----
__global__ void rvq_splitB_kernel(const float* __restrict__ cb)
{
    int id = blockIdx.x * 256 + threadIdx.x;
    int ck = id >> 6, d4 = id & 63;
    float4 v = *(const float4*)(cb + (size_t)ck * DDIM + d4 * 4);
    __nv_bfloat16 p1[4];
    p1[0] = __float2bfloat16_rn(v.x); p1[1] = __float2bfloat16_rn(v.y);
    p1[2] = __float2bfloat16_rn(v.z); p1[3] = __float2bfloat16_rn(v.w);
    *(uint64_t*)(g_B1 + (size_t)ck * 256 + d4 * 4) = *(uint64_t*)p1;
}
__global__ void rvq_ww_kernel(const float* __restrict__ cb)
{
    const int warp = threadIdx.x >> 5, lane = threadIdx.x & 31;
    const int k = blockIdx.x * 8 + warp;
    const float* w = cb + (size_t)k * DDIM;
    float s = 0.f;
    #pragma unroll
    for (int t = 0; t < 8; t++) { float v = w[lane + 32 * t]; s = fmaf(v, v, s); }
    #pragma unroll
    for (int o = 16; o; o >>= 1) s += __shfl_down_sync(0xffffffffu, s, o);
    if (lane == 0) g_ww[k] = s;
}

// ---- single fused kernel: all 8 stages, 2 CTAs/SM ----
__global__ void __launch_bounds__(TPB, 2)
rvq_fused_kernel(const float* __restrict__ z, const float* __restrict__ cb,
                 float* __restrict__ qOut, float* __restrict__ idxOut)
{
    extern __shared__ char smc[];
    const uint32_t sb = smem_u32(smc);
    int*   sIdx = (int*)(smc + SO_SIDX);
    float* rrsh = (float*)(smc + SO_RR);
    float* lp   = (float*)(smc + SO_LP);
    float* wws  = (float*)(smc + SO_WW);
    float* cv   = (float*)(smc + SO_CV);
    int*   ci   = (int*)(smc + SO_CI);

    const int tid  = threadIdx.x;
    const int lane = tid & 31;
    const int warp = tid >> 5;
    const int wr   = warp >> 2;      // 0..1 (32-row slice)
    const int wc   = warp & 3;       // 0..3 (32-col slice)
    const size_t rowbase = (size_t)blockIdx.x * BM;
    const int g = lane >> 2;

    const int arow0 = wr * 32 + (lane & 15);
    const int ukA = lane >> 4;
    const int ukB = (lane >> 3) & 1;
    const int brow_in = (lane & 7) + ((lane >> 4) << 3);
    const int erow = tid >> 2, eq = tid & 3;     // 4 threads/row phases
    const uint32_t qmask = 0xFu << (lane & ~3);  // quad-scoped shfl mask
    const int qbase = lane & ~3;

    // ---- stage-0 init: fill resident A (bf16, swizzled) + rr from z ----
    {
        const float* rp = z + (rowbase + erow) * DDIM;
        float s = 0.f;
        #pragma unroll
        for (int t = 0; t < 16; t++) {
            int d4 = eq + 4 * t;
            float4 v = *(const float4*)(rp + d4 * 4);
            __nv_bfloat16 p1[4];
            p1[0] = __float2bfloat16_rn(v.x); p1[1] = __float2bfloat16_rn(v.y);
            p1[2] = __float2bfloat16_rn(v.z); p1[3] = __float2bfloat16_rn(v.w);
            int u = d4 >> 1;
            *(uint64_t*)(smc + SO_A + erow * 512 + ((u ^ (erow & 7)) << 4) + (d4 & 1) * 8)
                = *(uint64_t*)p1;
            s = fmaf(v.x, v.x, s); s = fmaf(v.y, v.y, s);
            s = fmaf(v.z, v.z, s); s = fmaf(v.w, v.w, s);
        }
        s += __shfl_xor_sync(0xffffffffu, s, 1);
        s += __shfl_xor_sync(0xffffffffu, s, 2);
        if (eq == 0) rrsh[erow] = s;
    }
    __syncthreads();

    // B prefetch: tile (cq, nb, quarter) -> ring buffer b (128 cw x 64 dims = 16KB)
    auto pfB = [&](int cq, int nb_t, int q, int b) {
        const size_t base = ((size_t)(cq * KCB + nb_t * 128)) * 256 + q * 64;
        const uint32_t bbase = sb + SO_B + b * 16384;
        #pragma unroll
        for (int i = 0; i < 4; i++) {
            int v = tid + TPB * i;           // 1024 16B units
            int nrow = v >> 3, u = v & 7;
            cp16(bbase + nrow * 128 + ((u ^ (nrow & 7)) << 4),
                 g_B1 + base + (size_t)nrow * 256 + u * 8);
        }
    };

    // stage-0 tiles 0,1 -> ring bufs 0,1
    pfB(0, 0, 0, 0); CP_COMMIT();
    pfB(0, 0, 1, 1); CP_COMMIT();

    double lossAcc = 0.0;

    #pragma unroll 1
    for (int c = 0; c < NCB; c++) {
        const float* resIn = (c == 0) ? z : g_res;
        const float* cbc = cb + (size_t)c * KCB * DDIM;
        for (int i = tid; i < KCB; i += TPB) wws[i] = g_ww[c * KCB + i];

        float rrl[4];
        #pragma unroll
        for (int mf = 0; mf < 2; mf++)
            #pragma unroll
            for (int h = 0; h < 2; h++)
                rrl[mf * 2 + h] = rrsh[wr * 32 + mf * 16 + g + 8 * h];

        float cv4[16]; int ci4[16];
        #pragma unroll
        for (int i = 0; i < 16; i++) { cv4[i] = 3.0e38f; ci4[i] = 0x7fffffff; }

        float acc[2][4][4];

        // ---- mainloop: ONE barrier per k-iter (3-deep ring) ----
        #pragma unroll 1
        for (int kti = 0; kti < NKTI; kti++) {
            CP_WAIT(1);
            __syncthreads();
            // prefetch tile kti+2 into buf (kti+2)%3; its last readers were at
            // iter kti-1, fenced by this iteration's barrier. Empty commit when
            // past the end keeps wait_group accounting uniform.
            if (kti + 2 < NKTI) pfB(c, (kti + 2) >> 2, (kti + 2) & 3, (kti + 2) % 3);
            CP_COMMIT();

            const int nb = kti >> 2, kq = kti & 3;
            if (kq == 0) {
                #pragma unroll
                for (int mf = 0; mf < 2; mf++)
                    #pragma unroll
                    for (int j = 0; j < 4; j++)
                        #pragma unroll
                        for (int e = 0; e < 4; e++) acc[mf][j][e] = 0.f;
            }
            const uint32_t abase = sb + SO_A;
            const uint32_t bbase = sb + SO_B + (kti % 3) * 16384;
            #pragma unroll
            for (int s = 0; s < 4; s++) {
                uint32_t a[2][4];
                #pragma unroll
                for (int mf = 0; mf < 2; mf++) {
                    int r = arow0 + mf * 16;
                    int u = kq * 8 + s * 2 + ukA;
                    ldsm4(a[mf], abase + r * 512 + ((u ^ (r & 7)) << 4));
                }
                uint32_t b[4][2];
                #pragma unroll
                for (int nf4 = 0; nf4 < 2; nf4++) {
                    int r = wc * 32 + nf4 * 16 + brow_in;
                    int u = s * 2 + ukB;
                    uint32_t t[4];
                    ldsm4(t, bbase + r * 128 + ((u ^ (r & 7)) << 4));
                    b[nf4 * 2][0] = t[0]; b[nf4 * 2][1] = t[1];
                    b[nf4 * 2 + 1][0] = t[2]; b[nf4 * 2 + 1][1] = t[3];
                }
                #pragma unroll
                for (int mf = 0; mf < 2; mf++)
                    #pragma unroll
                    for (int j = 0; j < 4; j++)
                        mma16816(acc[mf][j], a[mf], b[j][0], b[j][1]);
            }

            if (kq == 3) {
                #pragma unroll
                for (int mf = 0; mf < 2; mf++) {
                    #pragma unroll
                    for (int h = 0; h < 2; h++) {
                        const int ridx = mf * 2 + h;
                        const float rrv = rrl[ridx];
                        #pragma unroll
                        for (int j = 0; j < 4; j++) {
                            #pragma unroll
                            for (int e = 0; e < 2; e++) {
                                int col = nb * 128 + wc * 32 + j * 8 + (lane & 3) * 2 + e;
                                float d2 = fmaf(-2.0f, acc[mf][j][h * 2 + e], rrv) + wws[col];
                                upd4(cv4 + ridx * 4, ci4 + ridx * 4, d2, col);
                            }
                        }
                    }
                }
            }
        }
        __syncthreads();   // all GEMM reads done; B ring now dead -> cv/ci overlay

        // dump best-4 lists: 64 rows x 64 slots (overlaid on B bufs 0,1)
        #pragma unroll
        for (int mf = 0; mf < 2; mf++)
            #pragma unroll
            for (int h = 0; h < 2; h++) {
                int row = wr * 32 + mf * 16 + g + 8 * h;
                int slot = wc * 16 + (lane & 3) * 4;
                #pragma unroll
                for (int s = 0; s < 4; s++) {
                    cv[row * 64 + slot + s] = cv4[(mf * 2 + h) * 4 + s];
                    ci[row * 64 + slot + s] = ci4[(mf * 2 + h) * 4 + s];
                }
            }
        __syncthreads();

        // exact rescore: candidates parallelized ACROSS the quad; each thread
        // runs the FULL sequential 256-FMA dot chain (bit-identical to the
        // reference-proven pipeline). rr quarters per-thread, identical chains,
        // combined ((q0+q1)+q2)+q3. Quad argmin = order-independent set-min.
        {
            const float* cvr = cv + erow * 64;
            const int*   cir = ci + erow * 64;
            float mv = cvr[0];
            #pragma unroll
            for (int s = 1; s < 64; s++) mv = fminf(mv, cvr[s]);
            const float band = 3e-3f;

            const float* rp = resIn + (rowbase + erow) * DDIM;
            float qv = 0.f;
            #pragma unroll
            for (int i = 0; i < 16; i++) {
                float4 v = *(const float4*)(rp + eq * 64 + i * 4);
                qv = fmaf(v.x, v.x, qv); qv = fmaf(v.y, v.y, qv);
                qv = fmaf(v.z, v.z, qv); qv = fmaf(v.w, v.w, qv);
            }
            float q0 = __shfl_sync(qmask, qv, qbase + 0);
            float q1 = __shfl_sync(qmask, qv, qbase + 1);
            float q2 = __shfl_sync(qmask, qv, qbase + 2);
            float q3 = __shfl_sync(qmask, qv, qbase + 3);
            float rr = ((q0 + q1) + q2) + q3;

            float bv = 3.0e38f; int bi = 0x7fffffff;
            #pragma unroll 1
            for (int s = eq; s < 64; s += 4) {       // uniform trip count (16)
                if (cvr[s] <= mv + band) {           // divergent; no collectives inside
                    int k = cir[s];
                    const float* w = cbc + (size_t)k * DDIM;
                    float acc2 = 0.f;
                    #pragma unroll 8
                    for (int i = 0; i < 64; i++) {   // full sequential 256-FMA chain
                        float4 rv = *(const float4*)(rp + i * 4);
                        float4 wv = *(const float4*)(w + i * 4);
                        acc2 = fmaf(rv.x, wv.x, acc2); acc2 = fmaf(rv.y, wv.y, acc2);
                        acc2 = fmaf(rv.z, wv.z, acc2); acc2 = fmaf(rv.w, wv.w, acc2);
                    }
                    float t  = fmaf(-2.0f, acc2, rr);
                    float d2 = t + wws[k];
                    if (d2 < bv || (d2 == bv && k < bi)) { bv = d2; bi = k; }
                }
            }
            #pragma unroll
            for (int o = 1; o <= 2; o <<= 1) {
                float ov = __shfl_xor_sync(qmask, bv, o);
                int   oi = __shfl_xor_sync(qmask, bi, o);
                if (ov < bv || (ov == bv && oi < bi)) { bv = ov; bi = oi; }
            }
            if (eq == 0) {
                sIdx[erow] = bi;
                if (idxOut) idxOut[(rowbase + erow) * NCB + c] = (float)bi;
            }
        }
        __syncthreads();   // rescore done reading cv/ci -> ring bufs reusable

        // next stage's first two B tiles (overlaps the long gmem epilogue)
        if (c + 1 < NCB) {
            pfB(c + 1, 0, 0, 0); CP_COMMIT();
            pfB(c + 1, 0, 1, 1); CP_COMMIT();
        }

        // epilogue: residual/quantized update + loss + next-stage A (smem) + rr
        {
            size_t grow = rowbase + erow;
            const float* wrow = cbc + (size_t)sIdx[erow] * DDIM;
            const float* rrow = resIn + grow * DDIM;
            float* ro = g_res + grow * DDIM;
            float* qo = qOut + grow * DDIM;
            float lsum = 0.f;
            #pragma unroll
            for (int t = 0; t < 16; t++) {
                int d4 = eq + 4 * t;
                float4 w4 = *(const float4*)(wrow + d4 * 4);
                float4 r4 = *(const float4*)(rrow + d4 * 4);
                float4 nr;
                nr.x = r4.x - w4.x; nr.y = r4.y - w4.y;
                nr.z = r4.z - w4.z; nr.w = r4.w - w4.w;
                *(float4*)(ro + d4 * 4) = nr;
                float4 qv2;
                if (c == 0) qv2 = w4;
                else {
                    float4 qp = *(const float4*)(qo + d4 * 4);
                    qv2.x = qp.x + w4.x; qv2.y = qp.y + w4.y;
                    qv2.z = qp.z + w4.z; qv2.w = qp.w + w4.w;
                }
                *(float4*)(qo + d4 * 4) = qv2;
                lsum = fmaf(nr.x, nr.x, lsum); lsum = fmaf(nr.y, nr.y, lsum);
                lsum = fmaf(nr.z, nr.z, lsum); lsum = fmaf(nr.w, nr.w, lsum);
                if (c < 7) {
                    __nv_bfloat16 p1[4];
                    p1[0] = __float2bfloat16_rn(nr.x); p1[1] = __float2bfloat16_rn(nr.y);
                    p1[2] = __float2bfloat16_rn(nr.z); p1[3] = __float2bfloat16_rn(nr.w);
                    int u = d4 >> 1;
                    *(uint64_t*)(smc + SO_A + erow * 512 + ((u ^ (erow & 7)) << 4) + (d4 & 1) * 8)
                        = *(uint64_t*)p1;
                }
            }
            // quad sum -> next-stage rr (filter only)
            float qsum = lsum;
            qsum += __shfl_xor_sync(0xffffffffu, qsum, 1);
            qsum += __shfl_xor_sync(0xffffffffu, qsum, 2);
            if (eq == 0) rrsh[erow] = qsum;
            // full warp sum -> loss partial
            float wsum = lsum;
            #pragma unroll
            for (int o = 16; o; o >>= 1) wsum += __shfl_xor_sync(0xffffffffu, wsum, o);
            if (lane == 0) lp[warp] = wsum;
        }
        __syncthreads();
        if (tid == 0) {
            double s = 0.0;
            #pragma unroll
            for (int w = 0; w < 8; w++) s += (double)lp[w];
            lossAcc += s;
        }
        __syncthreads();
    }
    if (tid == 0) g_lp[blockIdx.x] = lossAcc;
}

__global__ void rvq_loss_kernel(float* __restrict__ out, int lossOff)
{
    if (lossOff < 0) return;
    __shared__ double sd[256];
    int tid = threadIdx.x;
    double s = 0.0;
    for (int i = tid; i < NBLOCKS; i += 256) s += g_lp[i];
    sd[tid] = s;
    __syncthreads();
    for (int o = 128; o; o >>= 1) {
        if (tid < o) sd[tid] += sd[tid + o];
        __syncthreads();
    }
    if (tid == 0) out[lossOff] = (float)(sd[0] / (double)((long long)NROWS * DDIM));
}

extern "C" void kernel_launch(void* const* d_in, const int* in_sizes, int n_in,
                              void* d_out, int out_size)
{
    const float* z  = (const float*)d_in[0];
    const float* cb = (const float*)d_in[1];
    float* out = (float*)d_out;

    static bool attr_set = false;
    if (!attr_set) {
        cudaFuncSetAttribute(rvq_fused_kernel,
                             cudaFuncAttributeMaxDynamicSharedMemorySize, SMEMB);
        attr_set = true;
    }

    const int NZ = NROWS * DDIM, NIDX = NROWS * NCB;
    float* idxOut = nullptr;
    int lossOff = -1;
    if (out_size >= NZ + NIDX + 1) { idxOut = out + NZ; lossOff = NZ + NIDX; }
    else if (out_size == NZ + NIDX) { idxOut = out + NZ; }
    else if (out_size == NZ + 1)    { lossOff = NZ; }

    rvq_splitB_kernel<<<NCB * KCB * 64 / 256, 256>>>(cb);
    rvq_ww_kernel<<<NCB * KCB / 8, 256>>>(cb);
    rvq_fused_kernel<<<NBLOCKS, TPB, SMEMB>>>(z, cb, out, idxOut);
    rvq_loss_kernel<<<1, 256>>>(out, lossOff);
}